// round 1
// baseline (speedup 1.0000x reference)
#include <cuda_runtime.h>
#include <cuda_bf16.h>

// Problem constants
#define Bb 8
#define Cc 1024
#define INF 256
#define NH 8
#define OF 128
#define FEAT (NH*OF)          // 1024
#define ROWS (Bb*Cc)          // 8192
#define X_ELEMS (Bb*Cc*FEAT)  // 8388608  (relu(x) output elements)

// ---------------- device scratch (allocation-free rule: device globals) ----
__device__ float g_Wh[ROWS * FEAT];                 // (b,c,h,f) 33.5MB
__device__ float g_R [ROWS * FEAT];                 // H@res_W + res_b
__device__ float g_Hout[ROWS * FEAT];               // x = H_out + R
__device__ float g_es[ROWS * NH];
__device__ float g_ed[ROWS * NH];
__device__ float g_alphaT[(size_t)Bb * NH * Cc * Cc]; // (b,h,i,j) 268MB

// ---------------------------------------------------------------- K1: SGEMM
// C[M,N] = A[M,K] @ B[K,N] (+ bias).  128x128 tile, BK=8, 8x8 microtile.
template<int BIAS>
__global__ __launch_bounds__(256) void sgemm128(
    const float* __restrict__ A, const float* __restrict__ B,
    const float* __restrict__ bias, float* __restrict__ C,
    int K, int lda, int ldb, int ldc)
{
    __shared__ float As[8][128];
    __shared__ float Bs[8][128];
    const int tid = threadIdx.x;
    const int m0 = blockIdx.y * 128;
    const int n0 = blockIdx.x * 128;
    const int tx = tid & 15, ty = tid >> 4;

    float acc[8][8];
#pragma unroll
    for (int u = 0; u < 8; u++)
#pragma unroll
        for (int v = 0; v < 8; v++) acc[u][v] = 0.f;

    const int ar = tid >> 1, ak = (tid & 1) * 4;   // A: float4 at (row ar, k ak)
    const int bk = tid >> 5, bc = (tid & 31) * 4;  // B: float4 at (k bk, col bc)

    for (int k0 = 0; k0 < K; k0 += 8) {
        float4 av = *reinterpret_cast<const float4*>(&A[(size_t)(m0 + ar) * lda + k0 + ak]);
        As[ak + 0][ar] = av.x; As[ak + 1][ar] = av.y;
        As[ak + 2][ar] = av.z; As[ak + 3][ar] = av.w;
        *reinterpret_cast<float4*>(&Bs[bk][bc]) =
            *reinterpret_cast<const float4*>(&B[(size_t)(k0 + bk) * ldb + n0 + bc]);
        __syncthreads();
#pragma unroll
        for (int kk = 0; kk < 8; kk++) {
            float4 a0 = *reinterpret_cast<const float4*>(&As[kk][ty * 8]);
            float4 a1 = *reinterpret_cast<const float4*>(&As[kk][ty * 8 + 4]);
            float4 b0 = *reinterpret_cast<const float4*>(&Bs[kk][tx * 8]);
            float4 b1 = *reinterpret_cast<const float4*>(&Bs[kk][tx * 8 + 4]);
            float a[8] = {a0.x,a0.y,a0.z,a0.w,a1.x,a1.y,a1.z,a1.w};
            float b[8] = {b0.x,b0.y,b0.z,b0.w,b1.x,b1.y,b1.z,b1.w};
#pragma unroll
            for (int u = 0; u < 8; u++)
#pragma unroll
                for (int v = 0; v < 8; v++) acc[u][v] += a[u] * b[v];
        }
        __syncthreads();
    }
#pragma unroll
    for (int u = 0; u < 8; u++) {
        int row = m0 + ty * 8 + u;
#pragma unroll
        for (int v = 0; v < 8; v += 4) {
            int col = n0 + tx * 8 + v;
            float4 o = make_float4(acc[u][v], acc[u][v+1], acc[u][v+2], acc[u][v+3]);
            if (BIAS) { o.x += bias[col]; o.y += bias[col+1]; o.z += bias[col+2]; o.w += bias[col+3]; }
            *reinterpret_cast<float4*>(&C[(size_t)row * ldc + col]) = o;
        }
    }
}

// ---------------------------------------------- K2: attention score vectors
// e_src[b,c,h] = sum_f Wh[b,c,h,f]*a[h,f];  e_dst uses a[h,OF+f]
__global__ __launch_bounds__(256) void scores_kernel(const float* __restrict__ a_attn)
{
    const int bc = blockIdx.x;          // 0..8191
    const int w = threadIdx.x >> 5, l = threadIdx.x & 31;
    const float* whrow = g_Wh + (size_t)bc * FEAT + w * OF;
    const float* as = a_attn + w * (2 * OF);
    float s = 0.f, d = 0.f;
#pragma unroll
    for (int f = l; f < OF; f += 32) {
        float x = whrow[f];
        s += x * as[f];
        d += x * as[OF + f];
    }
#pragma unroll
    for (int o = 16; o; o >>= 1) {
        s += __shfl_xor_sync(0xffffffffu, s, o);
        d += __shfl_xor_sync(0xffffffffu, d, o);
    }
    if (!l) { g_es[bc * NH + w] = s; g_ed[bc * NH + w] = d; }
}

// ------------------------------------- K3: mask + leaky + A_norm + softmax
// One block per (b,i). Writes alpha (b,i,j,h) to d_out AND (b,h,i,j) scratch.
__global__ __launch_bounds__(256) void softmax_kernel(
    const float* __restrict__ Amat, float* __restrict__ alpha_out)
{
    __shared__ float sA[Cc];            // A row
    __shared__ float vals[Cc * 9];      // [j][h] padded stride 9 (36KB)
    __shared__ float s_es[8];
    __shared__ float s_stat[8];
    __shared__ float red[8][8];
    __shared__ float s_redsum[8];
    __shared__ float s_inv;

    const int bi = blockIdx.x;
    const int b = bi >> 10, i = bi & 1023;
    const int t = threadIdx.x, wid = t >> 5, lane = t & 31;

    const float* arow = Amat + (size_t)bi * Cc;
    float psum = 0.f;
#pragma unroll
    for (int jj = 0; jj < 4; jj++) {
        int j = t + jj * 256;
        float v = arow[j];
        sA[j] = v;
        psum += v;
    }
#pragma unroll
    for (int o = 16; o; o >>= 1) psum += __shfl_xor_sync(0xffffffffu, psum, o);
    if (!lane) s_redsum[wid] = psum;
    if (t < 8) s_es[t] = g_es[(size_t)bi * NH + t];
    __syncthreads();
    if (t == 0) {
        float s = 0.f;
#pragma unroll
        for (int w = 0; w < 8; w++) s += s_redsum[w];
        s_inv = 1.0f / (s + 1e-8f);
    }
    __syncthreads();

    const float inv = s_inv;
    float es[8];
#pragma unroll
    for (int h = 0; h < 8; h++) es[h] = s_es[h];

    const float INV_T = 1.0f / 1.5f;
    float lmax[8];
#pragma unroll
    for (int h = 0; h < 8; h++) lmax[h] = -3.4e38f;

#pragma unroll
    for (int jj = 0; jj < 4; jj++) {
        int j = t + jj * 256;
        const float4* edp = reinterpret_cast<const float4*>(g_ed + ((size_t)b * Cc + j) * NH);
        float4 e0 = edp[0], e1 = edp[1];
        float ed[8] = {e0.x,e0.y,e0.z,e0.w,e1.x,e1.y,e1.z,e1.w};
        float aval = sA[j];
        bool mk = (aval > 0.f) || (j == i);
        float An = aval * inv;
        float* vp = &vals[j * 9];
#pragma unroll
        for (int h = 0; h < 8; h++) {
            float s = es[h] + ed[h];
            s = s > 0.f ? s : 0.2f * s;            // leaky relu
            float v = ((mk ? s : -1e9f) + An) * INV_T;
            vp[h] = v;
            lmax[h] = fmaxf(lmax[h], v);
        }
    }
#pragma unroll
    for (int h = 0; h < 8; h++)
#pragma unroll
        for (int o = 16; o; o >>= 1)
            lmax[h] = fmaxf(lmax[h], __shfl_xor_sync(0xffffffffu, lmax[h], o));
    if (!lane) {
#pragma unroll
        for (int h = 0; h < 8; h++) red[wid][h] = lmax[h];
    }
    __syncthreads();
    if (t < 8) {
        float m = red[0][t];
#pragma unroll
        for (int w = 1; w < 8; w++) m = fmaxf(m, red[w][t]);
        s_stat[t] = m;
    }
    __syncthreads();
    float mh[8];
#pragma unroll
    for (int h = 0; h < 8; h++) mh[h] = s_stat[h];

    float lsum[8];
#pragma unroll
    for (int h = 0; h < 8; h++) lsum[h] = 0.f;
#pragma unroll
    for (int jj = 0; jj < 4; jj++) {
        int j = t + jj * 256;
        float* vp = &vals[j * 9];
#pragma unroll
        for (int h = 0; h < 8; h++) {
            float ev = __expf(vp[h] - mh[h]);
            vp[h] = ev;
            lsum[h] += ev;
        }
    }
#pragma unroll
    for (int h = 0; h < 8; h++)
#pragma unroll
        for (int o = 16; o; o >>= 1)
            lsum[h] += __shfl_xor_sync(0xffffffffu, lsum[h], o);
    __syncthreads();                    // red reuse: prior readers done
    if (!lane) {
#pragma unroll
        for (int h = 0; h < 8; h++) red[wid][h] = lsum[h];
    }
    __syncthreads();
    if (t < 8) {
        float s = 0.f;
#pragma unroll
        for (int w = 0; w < 8; w++) s += red[w][t];
        s_stat[t] = 1.0f / s;
    }
    __syncthreads();
    float ish[8];
#pragma unroll
    for (int h = 0; h < 8; h++) ish[h] = s_stat[h];

    // write alpha (b,i,j,h) to output — coalesced float4 pairs
    float* oa = alpha_out + (size_t)bi * (Cc * NH);
#pragma unroll
    for (int jj = 0; jj < 4; jj++) {
        int j = t + jj * 256;
        float* vp = &vals[j * 9];
        float4 o0 = make_float4(vp[0]*ish[0], vp[1]*ish[1], vp[2]*ish[2], vp[3]*ish[3]);
        float4 o1 = make_float4(vp[4]*ish[4], vp[5]*ish[5], vp[6]*ish[6], vp[7]*ish[7]);
        *reinterpret_cast<float4*>(oa + (size_t)j * NH)     = o0;
        *reinterpret_cast<float4*>(oa + (size_t)j * NH + 4) = o1;
    }
    // write alphaT (b,h,i,j) scratch — coalesced rows per head
#pragma unroll
    for (int h = 0; h < 8; h++) {
        float* ot = g_alphaT + (((size_t)(b * NH + h)) * Cc + i) * Cc;
        float s = ish[h];
#pragma unroll
        for (int jj = 0; jj < 4; jj++) {
            int j = t + jj * 256;
            ot[j] = vals[j * 9 + h] * s;
        }
    }
}

// ------------------------ K4: H_out = alpha @ Wh (+R), 64 batched GEMMs ----
// per (b,h): [1024 x 1024] @ [1024 x 128]. 128x128 tile (full N), BK=8.
__global__ __launch_bounds__(256) void aggr_gemm()
{
    __shared__ float As[8][128];
    __shared__ float Bs[8][128];
    const int z = blockIdx.z;
    const int b = z >> 3, h = z & 7;
    const float* A = g_alphaT + (size_t)z * (Cc * Cc);
    const float* B = g_Wh + (size_t)b * (Cc * FEAT) + h * OF;
    const float* R = g_R  + (size_t)b * (Cc * FEAT) + h * OF;
    float*       C = g_Hout + (size_t)b * (Cc * FEAT) + h * OF;
    const int m0 = blockIdx.y * 128;
    const int tid = threadIdx.x;
    const int tx = tid & 15, ty = tid >> 4;

    float acc[8][8];
#pragma unroll
    for (int u = 0; u < 8; u++)
#pragma unroll
        for (int v = 0; v < 8; v++) acc[u][v] = 0.f;

    const int ar = tid >> 1, ak = (tid & 1) * 4;
    const int bk = tid >> 5, bc = (tid & 31) * 4;

    for (int k0 = 0; k0 < Cc; k0 += 8) {
        float4 av = *reinterpret_cast<const float4*>(&A[(size_t)(m0 + ar) * Cc + k0 + ak]);
        As[ak + 0][ar] = av.x; As[ak + 1][ar] = av.y;
        As[ak + 2][ar] = av.z; As[ak + 3][ar] = av.w;
        *reinterpret_cast<float4*>(&Bs[bk][bc]) =
            *reinterpret_cast<const float4*>(&B[(size_t)(k0 + bk) * FEAT + bc]);
        __syncthreads();
#pragma unroll
        for (int kk = 0; kk < 8; kk++) {
            float4 a0 = *reinterpret_cast<const float4*>(&As[kk][ty * 8]);
            float4 a1 = *reinterpret_cast<const float4*>(&As[kk][ty * 8 + 4]);
            float4 b0 = *reinterpret_cast<const float4*>(&Bs[kk][tx * 8]);
            float4 b1 = *reinterpret_cast<const float4*>(&Bs[kk][tx * 8 + 4]);
            float a[8] = {a0.x,a0.y,a0.z,a0.w,a1.x,a1.y,a1.z,a1.w};
            float bb[8] = {b0.x,b0.y,b0.z,b0.w,b1.x,b1.y,b1.z,b1.w};
#pragma unroll
            for (int u = 0; u < 8; u++)
#pragma unroll
                for (int v = 0; v < 8; v++) acc[u][v] += a[u] * bb[v];
        }
        __syncthreads();
    }
#pragma unroll
    for (int u = 0; u < 8; u++) {
        int row = m0 + ty * 8 + u;
#pragma unroll
        for (int v = 0; v < 8; v += 4) {
            int col = tx * 8 + v;
            const float4 r4 = *reinterpret_cast<const float4*>(&R[(size_t)row * FEAT + col]);
            float4 o = make_float4(acc[u][v] + r4.x, acc[u][v+1] + r4.y,
                                   acc[u][v+2] + r4.z, acc[u][v+3] + r4.w);
            *reinterpret_cast<float4*>(&C[(size_t)row * FEAT + col]) = o;
        }
    }
}

// ------------------------------------------------- K5: LayerNorm + ReLU ----
__global__ __launch_bounds__(256) void ln_kernel(
    const float* __restrict__ gamma, const float* __restrict__ beta,
    float* __restrict__ out)
{
    __shared__ float rs[8], rs2[8];
    __shared__ float s_mu, s_rstd;
    const int bi = blockIdx.x;
    const int t = threadIdx.x, wid = t >> 5, lane = t & 31;
    const float* x = g_Hout + (size_t)bi * FEAT;
    float xs[4], s = 0.f, s2 = 0.f;
#pragma unroll
    for (int jj = 0; jj < 4; jj++) {
        float v = x[t + jj * 256];
        xs[jj] = v; s += v; s2 += v * v;
    }
#pragma unroll
    for (int o = 16; o; o >>= 1) {
        s  += __shfl_xor_sync(0xffffffffu, s, o);
        s2 += __shfl_xor_sync(0xffffffffu, s2, o);
    }
    if (!lane) { rs[wid] = s; rs2[wid] = s2; }
    __syncthreads();
    if (t == 0) {
        float ts = 0.f, ts2 = 0.f;
#pragma unroll
        for (int w = 0; w < 8; w++) { ts += rs[w]; ts2 += rs2[w]; }
        float mu = ts * (1.0f / FEAT);
        float var = ts2 * (1.0f / FEAT) - mu * mu;
        s_mu = mu;
        s_rstd = rsqrtf(var + 1e-5f);
    }
    __syncthreads();
    const float mu = s_mu, rstd = s_rstd;
#pragma unroll
    for (int jj = 0; jj < 4; jj++) {
        int f = t + jj * 256;
        float y = (xs[jj] - mu) * rstd * gamma[f] + beta[f];
        out[(size_t)bi * FEAT + f] = fmaxf(y, 0.f);
    }
}

// --------------------------------------------------------------------------
extern "C" void kernel_launch(void* const* d_in, const int* in_sizes, int n_in,
                              void* d_out, int out_size)
{
    const float* H      = (const float*)d_in[0];
    const float* Amat   = (const float*)d_in[1];
    const float* W      = (const float*)d_in[2];
    const float* a_attn = (const float*)d_in[3];
    const float* res_W  = (const float*)d_in[4];
    const float* res_b  = (const float*)d_in[5];
    const float* gamma  = (const float*)d_in[6];
    const float* beta   = (const float*)d_in[7];
    float* out = (float*)d_out;

    void *pWh = nullptr, *pR = nullptr;
    cudaGetSymbolAddress(&pWh, g_Wh);
    cudaGetSymbolAddress(&pR,  g_R);

    // K1: Wh = H @ W   and   R = H @ res_W + res_b
    dim3 g1(FEAT / 128, ROWS / 128, 1);
    sgemm128<0><<<g1, 256>>>(H, W,     nullptr, (float*)pWh, INF, INF, FEAT, FEAT);
    sgemm128<1><<<g1, 256>>>(H, res_W, res_b,   (float*)pR,  INF, INF, FEAT, FEAT);

    // K2: e_src / e_dst
    scores_kernel<<<ROWS, 256>>>(a_attn);

    // K3: masked leaky softmax -> alpha (both layouts)
    softmax_kernel<<<ROWS, 256>>>(Amat, out + X_ELEMS);

    // K4: H_out = alpha @ Wh + R
    dim3 g4(1, Cc / 128, Bb * NH);
    aggr_gemm<<<g4, 256>>>();

    // K5: LayerNorm + ReLU
    ln_kernel<<<ROWS, 256>>>(gamma, beta, out);
}

// round 2
// speedup vs baseline: 2.2224x; 2.2224x over previous
#include <cuda_runtime.h>
#include <cuda_bf16.h>
#include <cstdint>

// Problem constants
#define Bb 8
#define Cc 1024
#define INF 256
#define NH 8
#define OF 128
#define FEAT (NH*OF)          // 1024
#define ROWS (Bb*Cc)          // 8192
#define X_ELEMS (ROWS*FEAT)   // 8388608

// ---------------- device scratch ----
__device__ float g_Wh[ROWS * FEAT];                       // fp32 Wh (for scores)
__device__ __nv_bfloat16 g_Whb[ROWS * FEAT];              // bf16 Wh (for K4 B)
__device__ float g_R [ROWS * FEAT];                       // H@res_W + res_b
__device__ float g_Hout[ROWS * FEAT];                     // x
__device__ float g_es[ROWS * NH];
__device__ float g_ed[ROWS * NH];
__device__ __nv_bfloat16 g_alphaTb[(size_t)Bb * NH * Cc * Cc]; // (b,h,i,j) bf16

// ---------------- mma helpers ----
__device__ __forceinline__ uint32_t f2tf32(float x) {
    uint32_t r;
    asm("cvt.rna.tf32.f32 %0, %1;" : "=r"(r) : "f"(x));
    return r;
}
__device__ __forceinline__ void mma_tf32(float4& c, const uint32_t a[4],
                                         uint32_t b0, uint32_t b1) {
    asm volatile(
      "mma.sync.aligned.m16n8k8.row.col.f32.tf32.tf32.f32 "
      "{%0,%1,%2,%3},{%4,%5,%6,%7},{%8,%9},{%0,%1,%2,%3};"
      : "+f"(c.x), "+f"(c.y), "+f"(c.z), "+f"(c.w)
      : "r"(a[0]), "r"(a[1]), "r"(a[2]), "r"(a[3]), "r"(b0), "r"(b1));
}
__device__ __forceinline__ void mma_bf16(float4& c, const uint32_t a[4],
                                         uint32_t b0, uint32_t b1) {
    asm volatile(
      "mma.sync.aligned.m16n8k16.row.col.f32.bf16.bf16.f32 "
      "{%0,%1,%2,%3},{%4,%5,%6,%7},{%8,%9},{%0,%1,%2,%3};"
      : "+f"(c.x), "+f"(c.y), "+f"(c.z), "+f"(c.w)
      : "r"(a[0]), "r"(a[1]), "r"(a[2]), "r"(a[3]), "r"(b0), "r"(b1));
}

// =======================================================================
// K1: TF32 mma GEMM.  C[M,N] = A[M,K]@B[K,N] (+bias).
// Block tile 128x128, BK=16, 256 thr (8 warps, 4Mx2N grid, warp 32x64).
// SPLIT=1: 3xTF32 (hi/lo) for near-fp32 accuracy. WBF16: also emit bf16 C.
// =======================================================================
#define PADK 20    // words per As row (16 + 4 pad)
#define PADN 136   // words per Bs row (128 + 8 pad) -> conflict-free b-frags

template<int SPLIT, int BIAS, int WBF16>
__global__ __launch_bounds__(256) void gemm_tf32(
    const float* __restrict__ A, const float* __restrict__ B,
    const float* __restrict__ bias, float* __restrict__ C,
    __nv_bfloat16* __restrict__ Cb, int K, int lda, int ldb, int ldc)
{
    __shared__ uint32_t As [128 * PADK];
    __shared__ uint32_t Bs [16 * PADN];
    __shared__ uint32_t Asl[SPLIT ? 128 * PADK : 1];
    __shared__ uint32_t Bsl[SPLIT ? 16 * PADN : 1];

    const int tid  = threadIdx.x;
    const int m0   = blockIdx.y * 128, n0 = blockIdx.x * 128;
    const int wid  = tid >> 5, lane = tid & 31;
    const int wm   = (wid & 3) * 32, wn = (wid >> 2) * 64;
    const int g    = lane >> 2, tg = lane & 3;

    float4 acc[2][8];
#pragma unroll
    for (int mt = 0; mt < 2; mt++)
#pragma unroll
        for (int nt = 0; nt < 8; nt++) acc[mt][nt] = make_float4(0.f,0.f,0.f,0.f);

    float4 avs[2], bvs[2];

    auto loadg = [&](int k0) {
#pragma unroll
        for (int it = 0; it < 2; it++) {
            int idx = tid + it * 256;
            int r = idx >> 2, s = idx & 3;
            avs[it] = *reinterpret_cast<const float4*>(A + (size_t)(m0 + r) * lda + k0 + s * 4);
            int rb = idx >> 5, sb = idx & 31;
            bvs[it] = *reinterpret_cast<const float4*>(B + (size_t)(k0 + rb) * ldb + n0 + sb * 4);
        }
    };
    auto stage = [&]() {
#pragma unroll
        for (int it = 0; it < 2; it++) {
            int idx = tid + it * 256;
            int r = idx >> 2, s = idx & 3;
            float4 v = avs[it];
            uint4 hh = make_uint4(f2tf32(v.x), f2tf32(v.y), f2tf32(v.z), f2tf32(v.w));
            *reinterpret_cast<uint4*>(&As[r * PADK + s * 4]) = hh;
            if (SPLIT) {
                uint4 ll = make_uint4(f2tf32(v.x - __uint_as_float(hh.x)),
                                      f2tf32(v.y - __uint_as_float(hh.y)),
                                      f2tf32(v.z - __uint_as_float(hh.z)),
                                      f2tf32(v.w - __uint_as_float(hh.w)));
                *reinterpret_cast<uint4*>(&Asl[r * PADK + s * 4]) = ll;
            }
            int rb = idx >> 5, sb = idx & 31;
            v = bvs[it];
            uint4 hb = make_uint4(f2tf32(v.x), f2tf32(v.y), f2tf32(v.z), f2tf32(v.w));
            *reinterpret_cast<uint4*>(&Bs[rb * PADN + sb * 4]) = hb;
            if (SPLIT) {
                uint4 lb = make_uint4(f2tf32(v.x - __uint_as_float(hb.x)),
                                      f2tf32(v.y - __uint_as_float(hb.y)),
                                      f2tf32(v.z - __uint_as_float(hb.z)),
                                      f2tf32(v.w - __uint_as_float(hb.w)));
                *reinterpret_cast<uint4*>(&Bsl[rb * PADN + sb * 4]) = lb;
            }
        }
    };
    auto compute = [&]() {
#pragma unroll
        for (int kk = 0; kk < 16; kk += 8) {
            uint32_t ah[2][4], al[2][4];
#pragma unroll
            for (int mt = 0; mt < 2; mt++) {
                int r = wm + mt * 16 + g;
                ah[mt][0] = As[r       * PADK + kk + tg];
                ah[mt][1] = As[(r + 8) * PADK + kk + tg];
                ah[mt][2] = As[r       * PADK + kk + tg + 4];
                ah[mt][3] = As[(r + 8) * PADK + kk + tg + 4];
                if (SPLIT) {
                    al[mt][0] = Asl[r       * PADK + kk + tg];
                    al[mt][1] = Asl[(r + 8) * PADK + kk + tg];
                    al[mt][2] = Asl[r       * PADK + kk + tg + 4];
                    al[mt][3] = Asl[(r + 8) * PADK + kk + tg + 4];
                }
            }
#pragma unroll
            for (int nt = 0; nt < 8; nt++) {
                int cx = wn + nt * 8 + g;
                uint32_t b0 = Bs[(kk + tg)     * PADN + cx];
                uint32_t b1 = Bs[(kk + tg + 4) * PADN + cx];
#pragma unroll
                for (int mt = 0; mt < 2; mt++) mma_tf32(acc[mt][nt], ah[mt], b0, b1);
                if (SPLIT) {
                    uint32_t bl0 = Bsl[(kk + tg)     * PADN + cx];
                    uint32_t bl1 = Bsl[(kk + tg + 4) * PADN + cx];
#pragma unroll
                    for (int mt = 0; mt < 2; mt++) {
                        mma_tf32(acc[mt][nt], ah[mt], bl0, bl1);  // hi*lo
                        mma_tf32(acc[mt][nt], al[mt], b0, b1);    // lo*hi
                    }
                }
            }
        }
    };

    const int NIT = K / 16;
    loadg(0); stage();
    __syncthreads();
    for (int it = 0; it < NIT; it++) {
        if (it + 1 < NIT) loadg((it + 1) * 16);
        compute();
        __syncthreads();
        if (it + 1 < NIT) { stage(); __syncthreads(); }
    }

#pragma unroll
    for (int mt = 0; mt < 2; mt++) {
        int r0 = m0 + wm + mt * 16 + g;
#pragma unroll
        for (int nt = 0; nt < 8; nt++) {
            int cc = n0 + wn + nt * 8 + 2 * tg;
            float4 v = acc[mt][nt];
            float bv0 = 0.f, bv1 = 0.f;
            if (BIAS) { bv0 = bias[cc]; bv1 = bias[cc + 1]; }
            float2 p0 = make_float2(v.x + bv0, v.y + bv1);
            float2 p1 = make_float2(v.z + bv0, v.w + bv1);
            *reinterpret_cast<float2*>(C + (size_t)r0 * ldc + cc)       = p0;
            *reinterpret_cast<float2*>(C + (size_t)(r0 + 8) * ldc + cc) = p1;
            if (WBF16) {
                __nv_bfloat162 q0, q1;
                q0.x = __float2bfloat16(p0.x); q0.y = __float2bfloat16(p0.y);
                q1.x = __float2bfloat16(p1.x); q1.y = __float2bfloat16(p1.y);
                *reinterpret_cast<__nv_bfloat162*>(Cb + (size_t)r0 * ldc + cc)       = q0;
                *reinterpret_cast<__nv_bfloat162*>(Cb + (size_t)(r0 + 8) * ldc + cc) = q1;
            }
        }
    }
}

// ---------------------------------------------- K2: attention score vectors
__global__ __launch_bounds__(256) void scores_kernel(const float* __restrict__ a_attn)
{
    const int bc = blockIdx.x;
    const int w = threadIdx.x >> 5, l = threadIdx.x & 31;
    const float* whrow = g_Wh + (size_t)bc * FEAT + w * OF;
    const float* as = a_attn + w * (2 * OF);
    float s = 0.f, d = 0.f;
#pragma unroll
    for (int f = l; f < OF; f += 32) {
        float x = whrow[f];
        s += x * as[f];
        d += x * as[OF + f];
    }
#pragma unroll
    for (int o = 16; o; o >>= 1) {
        s += __shfl_xor_sync(0xffffffffu, s, o);
        d += __shfl_xor_sync(0xffffffffu, d, o);
    }
    if (!l) { g_es[bc * NH + w] = s; g_ed[bc * NH + w] = d; }
}

// ------------------------------------- K3: mask + leaky + A_norm + softmax
__global__ __launch_bounds__(256) void softmax_kernel(
    const float* __restrict__ Amat, float* __restrict__ alpha_out)
{
    __shared__ float sA[Cc];
    __shared__ float vals[Cc * 9];
    __shared__ float s_es[8];
    __shared__ float s_stat[8];
    __shared__ float red[8][8];
    __shared__ float s_redsum[8];
    __shared__ float s_inv;

    const int bi = blockIdx.x;
    const int b = bi >> 10, i = bi & 1023;
    const int t = threadIdx.x, wid = t >> 5, lane = t & 31;

    const float* arow = Amat + (size_t)bi * Cc;
    float psum = 0.f;
#pragma unroll
    for (int jj = 0; jj < 4; jj++) {
        int j = t + jj * 256;
        float v = arow[j];
        sA[j] = v;
        psum += v;
    }
#pragma unroll
    for (int o = 16; o; o >>= 1) psum += __shfl_xor_sync(0xffffffffu, psum, o);
    if (!lane) s_redsum[wid] = psum;
    if (t < 8) s_es[t] = g_es[(size_t)bi * NH + t];
    __syncthreads();
    if (t == 0) {
        float s = 0.f;
#pragma unroll
        for (int w = 0; w < 8; w++) s += s_redsum[w];
        s_inv = 1.0f / (s + 1e-8f);
    }
    __syncthreads();

    const float inv = s_inv;
    float es[8];
#pragma unroll
    for (int h = 0; h < 8; h++) es[h] = s_es[h];

    const float INV_T = 1.0f / 1.5f;
    float lmax[8];
#pragma unroll
    for (int h = 0; h < 8; h++) lmax[h] = -3.4e38f;

#pragma unroll
    for (int jj = 0; jj < 4; jj++) {
        int j = t + jj * 256;
        const float4* edp = reinterpret_cast<const float4*>(g_ed + ((size_t)b * Cc + j) * NH);
        float4 e0 = edp[0], e1 = edp[1];
        float ed[8] = {e0.x,e0.y,e0.z,e0.w,e1.x,e1.y,e1.z,e1.w};
        float aval = sA[j];
        bool mk = (aval > 0.f) || (j == i);
        float An = aval * inv;
        float* vp = &vals[j * 9];
#pragma unroll
        for (int h = 0; h < 8; h++) {
            float s = es[h] + ed[h];
            s = s > 0.f ? s : 0.2f * s;
            float v = ((mk ? s : -1e9f) + An) * INV_T;
            vp[h] = v;
            lmax[h] = fmaxf(lmax[h], v);
        }
    }
#pragma unroll
    for (int h = 0; h < 8; h++)
#pragma unroll
        for (int o = 16; o; o >>= 1)
            lmax[h] = fmaxf(lmax[h], __shfl_xor_sync(0xffffffffu, lmax[h], o));
    if (!lane) {
#pragma unroll
        for (int h = 0; h < 8; h++) red[wid][h] = lmax[h];
    }
    __syncthreads();
    if (t < 8) {
        float m = red[0][t];
#pragma unroll
        for (int w = 1; w < 8; w++) m = fmaxf(m, red[w][t]);
        s_stat[t] = m;
    }
    __syncthreads();
    float mh[8];
#pragma unroll
    for (int h = 0; h < 8; h++) mh[h] = s_stat[h];

    float lsum[8];
#pragma unroll
    for (int h = 0; h < 8; h++) lsum[h] = 0.f;
#pragma unroll
    for (int jj = 0; jj < 4; jj++) {
        int j = t + jj * 256;
        float* vp = &vals[j * 9];
#pragma unroll
        for (int h = 0; h < 8; h++) {
            float ev = __expf(vp[h] - mh[h]);
            vp[h] = ev;
            lsum[h] += ev;
        }
    }
#pragma unroll
    for (int h = 0; h < 8; h++)
#pragma unroll
        for (int o = 16; o; o >>= 1)
            lsum[h] += __shfl_xor_sync(0xffffffffu, lsum[h], o);
    __syncthreads();
    if (!lane) {
#pragma unroll
        for (int h = 0; h < 8; h++) red[wid][h] = lsum[h];
    }
    __syncthreads();
    if (t < 8) {
        float s = 0.f;
#pragma unroll
        for (int w = 0; w < 8; w++) s += red[w][t];
        s_stat[t] = 1.0f / s;
    }
    __syncthreads();
    float ish[8];
#pragma unroll
    for (int h = 0; h < 8; h++) ish[h] = s_stat[h];

    // alpha (b,i,j,h) fp32 to output
    float* oa = alpha_out + (size_t)bi * (Cc * NH);
#pragma unroll
    for (int jj = 0; jj < 4; jj++) {
        int j = t + jj * 256;
        float* vp = &vals[j * 9];
        float4 o0 = make_float4(vp[0]*ish[0], vp[1]*ish[1], vp[2]*ish[2], vp[3]*ish[3]);
        float4 o1 = make_float4(vp[4]*ish[4], vp[5]*ish[5], vp[6]*ish[6], vp[7]*ish[7]);
        *reinterpret_cast<float4*>(oa + (size_t)j * NH)     = o0;
        *reinterpret_cast<float4*>(oa + (size_t)j * NH + 4) = o1;
    }
    // alphaT (b,h,i,j) bf16 scratch for K4
#pragma unroll
    for (int h = 0; h < 8; h++) {
        __nv_bfloat16* ot = g_alphaTb + (((size_t)(b * NH + h)) * Cc + i) * Cc;
        float s = ish[h];
#pragma unroll
        for (int jj = 0; jj < 4; jj++) {
            int j = t + jj * 256;
            ot[j] = __float2bfloat16(vals[j * 9 + h] * s);
        }
    }
}

// =======================================================================
// K4: bf16 mma GEMM.  per (b,h): Hout[1024,128] = alphaT@Whb + R.
// Block tile 128x128 (N full), BK=32 bf16, 256 thr, warp 32x64.
// =======================================================================
#define PADKB 20   // words per As row (16 + 4)
#define PADNB 136  // words per Bs row (128 + 8)

__global__ __launch_bounds__(256) void aggr_bf16()
{
    __shared__ uint32_t As[128 * PADKB];  // [m][k/2] bf16x2 words
    __shared__ uint32_t Bs[16 * PADNB];   // [k/2][n] bf16x2 (k, k+1) words

    const int z = blockIdx.z;
    const int b = z >> 3, h = z & 7;
    const __nv_bfloat16* A  = g_alphaTb + (size_t)z * Cc * Cc;
    const __nv_bfloat16* Bp = g_Whb + (size_t)b * Cc * FEAT + h * OF;
    const float* R = g_R    + (size_t)b * Cc * FEAT + h * OF;
    float*       C = g_Hout + (size_t)b * Cc * FEAT + h * OF;

    const int m0 = blockIdx.y * 128;
    const int tid = threadIdx.x;
    const int wid = tid >> 5, lane = tid & 31;
    const int wm = (wid & 3) * 32, wn = (wid >> 2) * 64;
    const int g = lane >> 2, tg = lane & 3;

    float4 acc[2][8];
#pragma unroll
    for (int mt = 0; mt < 2; mt++)
#pragma unroll
        for (int nt = 0; nt < 8; nt++) acc[mt][nt] = make_float4(0.f,0.f,0.f,0.f);

    uint4 avs[2], bv0, bv1;

    auto loadg = [&](int k0) {
#pragma unroll
        for (int it = 0; it < 2; it++) {
            int idx = tid + it * 256;
            int r = idx >> 2, s = idx & 3;
            avs[it] = *reinterpret_cast<const uint4*>(A + (size_t)(m0 + r) * Cc + k0 + s * 8);
        }
        int rb = tid >> 4, sb = tid & 15;
        bv0 = *reinterpret_cast<const uint4*>(Bp + (size_t)(k0 + 2 * rb)     * FEAT + sb * 8);
        bv1 = *reinterpret_cast<const uint4*>(Bp + (size_t)(k0 + 2 * rb + 1) * FEAT + sb * 8);
    };
    auto stage = [&]() {
#pragma unroll
        for (int it = 0; it < 2; it++) {
            int idx = tid + it * 256;
            int r = idx >> 2, s = idx & 3;
            *reinterpret_cast<uint4*>(&As[r * PADKB + s * 4]) = avs[it];
        }
        int rb = tid >> 4, sb = tid & 15;
        uint32_t lo[4] = {bv0.x, bv0.y, bv0.z, bv0.w};
        uint32_t hi[4] = {bv1.x, bv1.y, bv1.z, bv1.w};
        uint32_t w[8];
#pragma unroll
        for (int j = 0; j < 4; j++) {
            w[2*j]   = (lo[j] & 0xffffu)  | (hi[j] << 16);
            w[2*j+1] = (lo[j] >> 16)      | (hi[j] & 0xffff0000u);
        }
        *reinterpret_cast<uint4*>(&Bs[rb * PADNB + sb * 8])     = make_uint4(w[0],w[1],w[2],w[3]);
        *reinterpret_cast<uint4*>(&Bs[rb * PADNB + sb * 8 + 4]) = make_uint4(w[4],w[5],w[6],w[7]);
    };
    auto compute = [&]() {
#pragma unroll
        for (int kk2 = 0; kk2 < 16; kk2 += 8) {   // two k16 steps per BK=32
            uint32_t af[2][4];
#pragma unroll
            for (int mt = 0; mt < 2; mt++) {
                int r = wm + mt * 16 + g;
                af[mt][0] = As[r       * PADKB + kk2 + tg];
                af[mt][1] = As[(r + 8) * PADKB + kk2 + tg];
                af[mt][2] = As[r       * PADKB + kk2 + tg + 4];
                af[mt][3] = As[(r + 8) * PADKB + kk2 + tg + 4];
            }
#pragma unroll
            for (int nt = 0; nt < 8; nt++) {
                int cx = wn + nt * 8 + g;
                uint32_t b0 = Bs[(kk2 + tg)     * PADNB + cx];
                uint32_t b1 = Bs[(kk2 + tg + 4) * PADNB + cx];
#pragma unroll
                for (int mt = 0; mt < 2; mt++) mma_bf16(acc[mt][nt], af[mt], b0, b1);
            }
        }
    };

    const int NIT = Cc / 32;   // 32
    loadg(0); stage();
    __syncthreads();
    for (int it = 0; it < NIT; it++) {
        if (it + 1 < NIT) loadg((it + 1) * 32);
        compute();
        __syncthreads();
        if (it + 1 < NIT) { stage(); __syncthreads(); }
    }

#pragma unroll
    for (int mt = 0; mt < 2; mt++) {
        int r0 = m0 + wm + mt * 16 + g;
#pragma unroll
        for (int nt = 0; nt < 8; nt++) {
            int cc = wn + nt * 8 + 2 * tg;
            float4 v = acc[mt][nt];
            float2 ra = *reinterpret_cast<const float2*>(R + (size_t)r0 * FEAT + cc);
            float2 rb = *reinterpret_cast<const float2*>(R + (size_t)(r0 + 8) * FEAT + cc);
            float2 p0 = make_float2(v.x + ra.x, v.y + ra.y);
            float2 p1 = make_float2(v.z + rb.x, v.w + rb.y);
            *reinterpret_cast<float2*>(C + (size_t)r0 * FEAT + cc)       = p0;
            *reinterpret_cast<float2*>(C + (size_t)(r0 + 8) * FEAT + cc) = p1;
        }
    }
}

// ------------------------------------------------- K5: LayerNorm + ReLU ----
__global__ __launch_bounds__(256) void ln_kernel(
    const float* __restrict__ gamma, const float* __restrict__ beta,
    float* __restrict__ out)
{
    __shared__ float rs[8], rs2[8];
    __shared__ float s_mu, s_rstd;
    const int bi = blockIdx.x;
    const int t = threadIdx.x, wid = t >> 5, lane = t & 31;
    const float* x = g_Hout + (size_t)bi * FEAT;
    float xs[4], s = 0.f, s2 = 0.f;
#pragma unroll
    for (int jj = 0; jj < 4; jj++) {
        float v = x[t + jj * 256];
        xs[jj] = v; s += v; s2 += v * v;
    }
#pragma unroll
    for (int o = 16; o; o >>= 1) {
        s  += __shfl_xor_sync(0xffffffffu, s, o);
        s2 += __shfl_xor_sync(0xffffffffu, s2, o);
    }
    if (!lane) { rs[wid] = s; rs2[wid] = s2; }
    __syncthreads();
    if (t == 0) {
        float ts = 0.f, ts2 = 0.f;
#pragma unroll
        for (int w = 0; w < 8; w++) { ts += rs[w]; ts2 += rs2[w]; }
        float mu = ts * (1.0f / FEAT);
        float var = ts2 * (1.0f / FEAT) - mu * mu;
        s_mu = mu;
        s_rstd = rsqrtf(var + 1e-5f);
    }
    __syncthreads();
    const float mu = s_mu, rstd = s_rstd;
#pragma unroll
    for (int jj = 0; jj < 4; jj++) {
        int f = t + jj * 256;
        float y = (xs[jj] - mu) * rstd * gamma[f] + beta[f];
        out[(size_t)bi * FEAT + f] = fmaxf(y, 0.f);
    }
}

// --------------------------------------------------------------------------
extern "C" void kernel_launch(void* const* d_in, const int* in_sizes, int n_in,
                              void* d_out, int out_size)
{
    const float* H      = (const float*)d_in[0];
    const float* Amat   = (const float*)d_in[1];
    const float* W      = (const float*)d_in[2];
    const float* a_attn = (const float*)d_in[3];
    const float* res_W  = (const float*)d_in[4];
    const float* res_b  = (const float*)d_in[5];
    const float* gamma  = (const float*)d_in[6];
    const float* beta   = (const float*)d_in[7];
    float* out = (float*)d_out;

    void *pWh = nullptr, *pWhb = nullptr, *pR = nullptr;
    cudaGetSymbolAddress(&pWh,  g_Wh);
    cudaGetSymbolAddress(&pWhb, g_Whb);
    cudaGetSymbolAddress(&pR,   g_R);

    dim3 g1(FEAT / 128, ROWS / 128, 1);  // 8 x 64
    // Wh = H @ W  (tf32 single-pass; fp32 + bf16 outputs)
    gemm_tf32<0, 0, 1><<<g1, 256>>>(H, W, nullptr, (float*)pWh,
                                    (__nv_bfloat16*)pWhb, INF, INF, FEAT, FEAT);
    // R = H @ res_W + res_b  (3xTF32: near-fp32 precision)
    gemm_tf32<1, 1, 0><<<g1, 256>>>(H, res_W, res_b, (float*)pR,
                                    nullptr, INF, INF, FEAT, FEAT);

    scores_kernel<<<ROWS, 256>>>(a_attn);
    softmax_kernel<<<ROWS, 256>>>(Amat, out + X_ELEMS);

    dim3 g4(1, Cc / 128, Bb * NH);
    aggr_bf16<<<g4, 256>>>();

    ln_kernel<<<ROWS, 256>>>(gamma, beta, out);
}

// round 3
// speedup vs baseline: 2.5384x; 1.1421x over previous
#include <cuda_runtime.h>
#include <cuda_bf16.h>
#include <cstdint>

// Problem constants
#define Bb 8
#define Cc 1024
#define INF 256
#define NH 8
#define OF 128
#define FEAT (NH*OF)          // 1024
#define ROWS (Bb*Cc)          // 8192
#define X_ELEMS (ROWS*FEAT)   // 8388608

// ---------------- device scratch ----
__device__ float g_Wh[ROWS * FEAT];                       // fp32 Wh (for scores)
__device__ __nv_bfloat16 g_Whb[ROWS * FEAT];              // bf16 Wh (for K4 B)
__device__ float g_R [ROWS * FEAT];                       // H@res_W + res_b
__device__ float g_Hout[ROWS * FEAT];                     // x
__device__ float g_es[ROWS * NH];
__device__ float g_ed[ROWS * NH];
__device__ __nv_bfloat16 g_alphaTb[(size_t)Bb * NH * Cc * Cc]; // (b,h,i,j) bf16

// ---------------- helpers ----
__device__ __forceinline__ void mma_bf16(float4& c, const uint32_t a[4],
                                         uint32_t b0, uint32_t b1) {
    asm volatile(
      "mma.sync.aligned.m16n8k16.row.col.f32.bf16.bf16.f32 "
      "{%0,%1,%2,%3},{%4,%5,%6,%7},{%8,%9},{%0,%1,%2,%3};"
      : "+f"(c.x), "+f"(c.y), "+f"(c.z), "+f"(c.w)
      : "r"(a[0]), "r"(a[1]), "r"(a[2]), "r"(a[3]), "r"(b0), "r"(b1));
}
__device__ __forceinline__ uint32_t packbf(float x, float y) {
    __nv_bfloat162 t;
    t.x = __float2bfloat16(x); t.y = __float2bfloat16(y);
    return *reinterpret_cast<uint32_t*>(&t);
}

// =======================================================================
// K1: split-bf16 3-term GEMM: C = A@B (+bias), near-fp32 accuracy.
// A fp32 [M,K] row-major, B fp32 [K,N]. Tile 128x128, BK=16, 256 thr.
// Double-buffered SMEM, one sync per iter. WBF16: also emit bf16 C.
// =======================================================================
#define PA 12     // A row words (8 bf16x2 + 4 pad)
#define PB 136    // B row words (128 + 8 pad)

template<int BIAS, int WBF16>
__global__ __launch_bounds__(256) void gemm_bf16x3(
    const float* __restrict__ A, const float* __restrict__ B,
    const float* __restrict__ bias, float* __restrict__ C,
    __nv_bfloat16* __restrict__ Cb, int K, int lda, int ldb, int ldc)
{
    __shared__ uint32_t Ah[2][128 * PA];
    __shared__ uint32_t Al[2][128 * PA];
    __shared__ uint32_t Bh[2][8 * PB];
    __shared__ uint32_t Bl[2][8 * PB];

    const int tid  = threadIdx.x;
    const int m0   = blockIdx.y * 128, n0 = blockIdx.x * 128;
    const int wid  = tid >> 5, lane = tid & 31;
    const int wm   = (wid & 3) * 32, wn = (wid >> 2) * 64;
    const int g    = lane >> 2, tg = lane & 3;

    float4 acc[2][8];
#pragma unroll
    for (int mt = 0; mt < 2; mt++)
#pragma unroll
        for (int nt = 0; nt < 8; nt++) acc[mt][nt] = make_float4(0.f,0.f,0.f,0.f);

    float4 avs[2], b0v, b1v;
    const int ar = tid >> 2, as_ = tid & 3;        // A: 2 float4 per thread
    const int rb = tid >> 5, cb = tid & 31;        // B: k-pair rb, cols cb*4

    auto loadg = [&](int k0) {
#pragma unroll
        for (int it = 0; it < 2; it++) {
            int r = ar + it * 64;
            avs[it] = *reinterpret_cast<const float4*>(A + (size_t)(m0 + r) * lda + k0 + as_ * 4);
        }
        b0v = *reinterpret_cast<const float4*>(B + (size_t)(k0 + 2 * rb)     * ldb + n0 + cb * 4);
        b1v = *reinterpret_cast<const float4*>(B + (size_t)(k0 + 2 * rb + 1) * ldb + n0 + cb * 4);
    };
    auto stage = [&](int buf) {
#pragma unroll
        for (int it = 0; it < 2; it++) {
            int r = ar + it * 64;
            float4 v = avs[it];
            float hx = __bfloat162float(__float2bfloat16(v.x));
            float hy = __bfloat162float(__float2bfloat16(v.y));
            float hz = __bfloat162float(__float2bfloat16(v.z));
            float hw = __bfloat162float(__float2bfloat16(v.w));
            uint2 wh = make_uint2(packbf(v.x, v.y), packbf(v.z, v.w));
            uint2 wl = make_uint2(packbf(v.x - hx, v.y - hy), packbf(v.z - hz, v.w - hw));
            *reinterpret_cast<uint2*>(&Ah[buf][r * PA + as_ * 2]) = wh;
            *reinterpret_cast<uint2*>(&Al[buf][r * PA + as_ * 2]) = wl;
        }
        float p0[4] = {b0v.x, b0v.y, b0v.z, b0v.w};
        float p1[4] = {b1v.x, b1v.y, b1v.z, b1v.w};
        uint32_t wh[4], wl[4];
#pragma unroll
        for (int j = 0; j < 4; j++) {
            float h0 = __bfloat162float(__float2bfloat16(p0[j]));
            float h1 = __bfloat162float(__float2bfloat16(p1[j]));
            wh[j] = packbf(p0[j], p1[j]);
            wl[j] = packbf(p0[j] - h0, p1[j] - h1);
        }
        *reinterpret_cast<uint4*>(&Bh[buf][rb * PB + cb * 4]) = make_uint4(wh[0],wh[1],wh[2],wh[3]);
        *reinterpret_cast<uint4*>(&Bl[buf][rb * PB + cb * 4]) = make_uint4(wl[0],wl[1],wl[2],wl[3]);
    };
    auto compute = [&](int buf) {
        uint32_t ah[2][4], al[2][4];
#pragma unroll
        for (int mt = 0; mt < 2; mt++) {
            int r = wm + mt * 16 + g;
            ah[mt][0] = Ah[buf][r       * PA + tg];
            ah[mt][1] = Ah[buf][(r + 8) * PA + tg];
            ah[mt][2] = Ah[buf][r       * PA + tg + 4];
            ah[mt][3] = Ah[buf][(r + 8) * PA + tg + 4];
            al[mt][0] = Al[buf][r       * PA + tg];
            al[mt][1] = Al[buf][(r + 8) * PA + tg];
            al[mt][2] = Al[buf][r       * PA + tg + 4];
            al[mt][3] = Al[buf][(r + 8) * PA + tg + 4];
        }
#pragma unroll
        for (int nt = 0; nt < 8; nt++) {
            int cx = wn + nt * 8 + g;
            uint32_t bh0 = Bh[buf][tg       * PB + cx];
            uint32_t bh1 = Bh[buf][(tg + 4) * PB + cx];
            uint32_t bl0 = Bl[buf][tg       * PB + cx];
            uint32_t bl1 = Bl[buf][(tg + 4) * PB + cx];
#pragma unroll
            for (int mt = 0; mt < 2; mt++) {
                mma_bf16(acc[mt][nt], ah[mt], bh0, bh1);
                mma_bf16(acc[mt][nt], ah[mt], bl0, bl1);
                mma_bf16(acc[mt][nt], al[mt], bh0, bh1);
            }
        }
    };

    const int NIT = K / 16;
    loadg(0); stage(0);
    __syncthreads();
    for (int it = 0; it < NIT; it++) {
        if (it + 1 < NIT) loadg((it + 1) * 16);
        compute(it & 1);
        if (it + 1 < NIT) stage((it + 1) & 1);
        __syncthreads();
    }

#pragma unroll
    for (int mt = 0; mt < 2; mt++) {
        int r0 = m0 + wm + mt * 16 + g;
#pragma unroll
        for (int nt = 0; nt < 8; nt++) {
            int cc = n0 + wn + nt * 8 + 2 * tg;
            float4 v = acc[mt][nt];
            float bv0 = 0.f, bv1 = 0.f;
            if (BIAS) { bv0 = bias[cc]; bv1 = bias[cc + 1]; }
            float2 p0 = make_float2(v.x + bv0, v.y + bv1);
            float2 p1 = make_float2(v.z + bv0, v.w + bv1);
            *reinterpret_cast<float2*>(C + (size_t)r0 * ldc + cc)       = p0;
            *reinterpret_cast<float2*>(C + (size_t)(r0 + 8) * ldc + cc) = p1;
            if (WBF16) {
                __nv_bfloat162 q0, q1;
                q0.x = __float2bfloat16(p0.x); q0.y = __float2bfloat16(p0.y);
                q1.x = __float2bfloat16(p1.x); q1.y = __float2bfloat16(p1.y);
                *reinterpret_cast<__nv_bfloat162*>(Cb + (size_t)r0 * ldc + cc)       = q0;
                *reinterpret_cast<__nv_bfloat162*>(Cb + (size_t)(r0 + 8) * ldc + cc) = q1;
            }
        }
    }
}

// ---------------------------------------------- K2: attention score vectors
__global__ __launch_bounds__(256) void scores_kernel(const float* __restrict__ a_attn)
{
    const int bc = blockIdx.x;
    const int w = threadIdx.x >> 5, l = threadIdx.x & 31;
    const float* whrow = g_Wh + (size_t)bc * FEAT + w * OF;
    const float* as = a_attn + w * (2 * OF);
    float s = 0.f, d = 0.f;
#pragma unroll
    for (int f = l; f < OF; f += 32) {
        float x = whrow[f];
        s += x * as[f];
        d += x * as[OF + f];
    }
#pragma unroll
    for (int o = 16; o; o >>= 1) {
        s += __shfl_xor_sync(0xffffffffu, s, o);
        d += __shfl_xor_sync(0xffffffffu, d, o);
    }
    if (!l) { g_es[bc * NH + w] = s; g_ed[bc * NH + w] = d; }
}

// ------------------------------------- K3: softmax, register-resident
// One block per (b,i,half). Each thread: 4 j x 4 heads in registers.
__global__ __launch_bounds__(256) void softmax_kernel(
    const float* __restrict__ Amat, float* __restrict__ alpha_out)
{
    __shared__ float s_es[4];
    __shared__ float s_stat[4];
    __shared__ float red[8][4];
    __shared__ float s_redsum[8];
    __shared__ float s_inv;

    const int bi2 = blockIdx.x;
    const int bi = bi2 >> 1, half = bi2 & 1;
    const int b = bi >> 10, i = bi & 1023;
    const int t = threadIdx.x, wid = t >> 5, lane = t & 31;

    const float* arow = Amat + (size_t)bi * Cc;
    float av[4], psum = 0.f;
#pragma unroll
    for (int jj = 0; jj < 4; jj++) {
        int j = t + jj * 256;
        av[jj] = arow[j];
        psum += av[jj];
    }
#pragma unroll
    for (int o = 16; o; o >>= 1) psum += __shfl_xor_sync(0xffffffffu, psum, o);
    if (!lane) s_redsum[wid] = psum;
    if (t < 4) s_es[t] = g_es[(size_t)bi * NH + half * 4 + t];
    __syncthreads();
    if (t == 0) {
        float s = 0.f;
#pragma unroll
        for (int w = 0; w < 8; w++) s += s_redsum[w];
        s_inv = 1.0f / (s + 1e-8f);
    }
    __syncthreads();

    const float inv = s_inv;
    float es[4];
#pragma unroll
    for (int h = 0; h < 4; h++) es[h] = s_es[h];

    const float INV_T = 1.0f / 1.5f;
    float vv[4][4];
    float lmax[4] = {-3.4e38f, -3.4e38f, -3.4e38f, -3.4e38f};

#pragma unroll
    for (int jj = 0; jj < 4; jj++) {
        int j = t + jj * 256;
        float4 e4 = *reinterpret_cast<const float4*>(g_ed + ((size_t)b * Cc + j) * NH + half * 4);
        float ed[4] = {e4.x, e4.y, e4.z, e4.w};
        float aval = av[jj];
        bool mk = (aval > 0.f) || (j == i);
        float An = aval * inv;
#pragma unroll
        for (int h = 0; h < 4; h++) {
            float s = es[h] + ed[h];
            s = s > 0.f ? s : 0.2f * s;            // leaky relu
            float v = ((mk ? s : -1e9f) + An) * INV_T;
            vv[jj][h] = v;
            lmax[h] = fmaxf(lmax[h], v);
        }
    }
#pragma unroll
    for (int h = 0; h < 4; h++)
#pragma unroll
        for (int o = 16; o; o >>= 1)
            lmax[h] = fmaxf(lmax[h], __shfl_xor_sync(0xffffffffu, lmax[h], o));
    if (!lane) {
#pragma unroll
        for (int h = 0; h < 4; h++) red[wid][h] = lmax[h];
    }
    __syncthreads();
    if (t < 4) {
        float m = red[0][t];
#pragma unroll
        for (int w = 1; w < 8; w++) m = fmaxf(m, red[w][t]);
        s_stat[t] = m;
    }
    __syncthreads();
    float mh[4];
#pragma unroll
    for (int h = 0; h < 4; h++) mh[h] = s_stat[h];

    float lsum[4] = {0.f, 0.f, 0.f, 0.f};
#pragma unroll
    for (int jj = 0; jj < 4; jj++)
#pragma unroll
        for (int h = 0; h < 4; h++) {
            float ev = __expf(vv[jj][h] - mh[h]);
            vv[jj][h] = ev;
            lsum[h] += ev;
        }
#pragma unroll
    for (int h = 0; h < 4; h++)
#pragma unroll
        for (int o = 16; o; o >>= 1)
            lsum[h] += __shfl_xor_sync(0xffffffffu, lsum[h], o);
    if (!lane) {
#pragma unroll
        for (int h = 0; h < 4; h++) red[wid][h] = lsum[h];
    }
    __syncthreads();
    if (t < 4) {
        float s = 0.f;
#pragma unroll
        for (int w = 0; w < 8; w++) s += red[w][t];
        s_stat[t] = 1.0f / s;
    }
    __syncthreads();
    float ish[4];
#pragma unroll
    for (int h = 0; h < 4; h++) ish[h] = s_stat[h];

    // alpha (b,i,j,h) fp32 output
    float* oa = alpha_out + (size_t)bi * (Cc * NH) + half * 4;
#pragma unroll
    for (int jj = 0; jj < 4; jj++) {
        int j = t + jj * 256;
        float4 o0 = make_float4(vv[jj][0]*ish[0], vv[jj][1]*ish[1],
                                vv[jj][2]*ish[2], vv[jj][3]*ish[3]);
        *reinterpret_cast<float4*>(oa + (size_t)j * NH) = o0;
    }
    // alphaT (b,h,i,j) bf16 scratch for K4
#pragma unroll
    for (int h = 0; h < 4; h++) {
        int hg = half * 4 + h;
        __nv_bfloat16* ot = g_alphaTb + (((size_t)(b * NH + hg)) * Cc + i) * Cc;
        float s = ish[h];
#pragma unroll
        for (int jj = 0; jj < 4; jj++) {
            int j = t + jj * 256;
            ot[j] = __float2bfloat16(vv[jj][h] * s);
        }
    }
}

// =======================================================================
// K4: bf16 mma GEMM.  per (b,h): Hout[1024,128] = alphaT@Whb + R.
// 128x128 tile (full N), BK=32, 256 thr, double-buffered.
// =======================================================================
#define PADKB 20   // words per As row (16 + 4)
#define PADNB 136  // words per Bs row (128 + 8)

__global__ __launch_bounds__(256) void aggr_bf16()
{
    __shared__ uint32_t As[2][128 * PADKB];
    __shared__ uint32_t Bs[2][16 * PADNB];

    const int z = blockIdx.z;
    const int b = z >> 3, h = z & 7;
    const __nv_bfloat16* A  = g_alphaTb + (size_t)z * Cc * Cc;
    const __nv_bfloat16* Bp = g_Whb + (size_t)b * Cc * FEAT + h * OF;
    const float* R = g_R    + (size_t)b * Cc * FEAT + h * OF;
    float*       C = g_Hout + (size_t)b * Cc * FEAT + h * OF;

    const int m0 = blockIdx.y * 128;
    const int tid = threadIdx.x;
    const int wid = tid >> 5, lane = tid & 31;
    const int wm = (wid & 3) * 32, wn = (wid >> 2) * 64;
    const int g = lane >> 2, tg = lane & 3;

    float4 acc[2][8];
#pragma unroll
    for (int mt = 0; mt < 2; mt++)
#pragma unroll
        for (int nt = 0; nt < 8; nt++) acc[mt][nt] = make_float4(0.f,0.f,0.f,0.f);

    uint4 avs[2], bv0, bv1;
    const int ar = tid >> 2, as_ = tid & 3;
    const int rb = tid >> 4, sb = tid & 15;

    auto loadg = [&](int k0) {
#pragma unroll
        for (int it = 0; it < 2; it++) {
            int r = ar + it * 64;
            avs[it] = *reinterpret_cast<const uint4*>(A + (size_t)(m0 + r) * Cc + k0 + as_ * 8);
        }
        bv0 = *reinterpret_cast<const uint4*>(Bp + (size_t)(k0 + 2 * rb)     * FEAT + sb * 8);
        bv1 = *reinterpret_cast<const uint4*>(Bp + (size_t)(k0 + 2 * rb + 1) * FEAT + sb * 8);
    };
    auto stage = [&](int buf) {
#pragma unroll
        for (int it = 0; it < 2; it++) {
            int r = ar + it * 64;
            *reinterpret_cast<uint4*>(&As[buf][r * PADKB + as_ * 4]) = avs[it];
        }
        uint32_t lo[4] = {bv0.x, bv0.y, bv0.z, bv0.w};
        uint32_t hi[4] = {bv1.x, bv1.y, bv1.z, bv1.w};
        uint32_t w[8];
#pragma unroll
        for (int j = 0; j < 4; j++) {
            w[2*j]   = (lo[j] & 0xffffu)  | (hi[j] << 16);
            w[2*j+1] = (lo[j] >> 16)      | (hi[j] & 0xffff0000u);
        }
        *reinterpret_cast<uint4*>(&Bs[buf][rb * PADNB + sb * 8])     = make_uint4(w[0],w[1],w[2],w[3]);
        *reinterpret_cast<uint4*>(&Bs[buf][rb * PADNB + sb * 8 + 4]) = make_uint4(w[4],w[5],w[6],w[7]);
    };
    auto compute = [&](int buf) {
#pragma unroll
        for (int kk2 = 0; kk2 < 16; kk2 += 8) {
            uint32_t af[2][4];
#pragma unroll
            for (int mt = 0; mt < 2; mt++) {
                int r = wm + mt * 16 + g;
                af[mt][0] = As[buf][r       * PADKB + kk2 + tg];
                af[mt][1] = As[buf][(r + 8) * PADKB + kk2 + tg];
                af[mt][2] = As[buf][r       * PADKB + kk2 + tg + 4];
                af[mt][3] = As[buf][(r + 8) * PADKB + kk2 + tg + 4];
            }
#pragma unroll
            for (int nt = 0; nt < 8; nt++) {
                int cx = wn + nt * 8 + g;
                uint32_t b0 = Bs[buf][(kk2 + tg)     * PADNB + cx];
                uint32_t b1 = Bs[buf][(kk2 + tg + 4) * PADNB + cx];
#pragma unroll
                for (int mt = 0; mt < 2; mt++) mma_bf16(acc[mt][nt], af[mt], b0, b1);
            }
        }
    };

    const int NIT = Cc / 32;   // 32
    loadg(0); stage(0);
    __syncthreads();
    for (int it = 0; it < NIT; it++) {
        if (it + 1 < NIT) loadg((it + 1) * 32);
        compute(it & 1);
        if (it + 1 < NIT) stage((it + 1) & 1);
        __syncthreads();
    }

#pragma unroll
    for (int mt = 0; mt < 2; mt++) {
        int r0 = m0 + wm + mt * 16 + g;
#pragma unroll
        for (int nt = 0; nt < 8; nt++) {
            int cc = wn + nt * 8 + 2 * tg;
            float4 v = acc[mt][nt];
            float2 ra = *reinterpret_cast<const float2*>(R + (size_t)r0 * FEAT + cc);
            float2 rbv = *reinterpret_cast<const float2*>(R + (size_t)(r0 + 8) * FEAT + cc);
            float2 p0 = make_float2(v.x + ra.x,  v.y + ra.y);
            float2 p1 = make_float2(v.z + rbv.x, v.w + rbv.y);
            *reinterpret_cast<float2*>(C + (size_t)r0 * FEAT + cc)       = p0;
            *reinterpret_cast<float2*>(C + (size_t)(r0 + 8) * FEAT + cc) = p1;
        }
    }
}

// ------------------------------------------------- K5: LayerNorm + ReLU ----
__global__ __launch_bounds__(256) void ln_kernel(
    const float* __restrict__ gamma, const float* __restrict__ beta,
    float* __restrict__ out)
{
    __shared__ float rs[8], rs2[8];
    __shared__ float s_mu, s_rstd;
    const int bi = blockIdx.x;
    const int t = threadIdx.x, wid = t >> 5, lane = t & 31;
    const float* x = g_Hout + (size_t)bi * FEAT;
    float xs[4], s = 0.f, s2 = 0.f;
#pragma unroll
    for (int jj = 0; jj < 4; jj++) {
        float v = x[t + jj * 256];
        xs[jj] = v; s += v; s2 += v * v;
    }
#pragma unroll
    for (int o = 16; o; o >>= 1) {
        s  += __shfl_xor_sync(0xffffffffu, s, o);
        s2 += __shfl_xor_sync(0xffffffffu, s2, o);
    }
    if (!lane) { rs[wid] = s; rs2[wid] = s2; }
    __syncthreads();
    if (t == 0) {
        float ts = 0.f, ts2 = 0.f;
#pragma unroll
        for (int w = 0; w < 8; w++) { ts += rs[w]; ts2 += rs2[w]; }
        float mu = ts * (1.0f / FEAT);
        float var = ts2 * (1.0f / FEAT) - mu * mu;
        s_mu = mu;
        s_rstd = rsqrtf(var + 1e-5f);
    }
    __syncthreads();
    const float mu = s_mu, rstd = s_rstd;
#pragma unroll
    for (int jj = 0; jj < 4; jj++) {
        int f = t + jj * 256;
        float y = (xs[jj] - mu) * rstd * gamma[f] + beta[f];
        out[(size_t)bi * FEAT + f] = fmaxf(y, 0.f);
    }
}

// --------------------------------------------------------------------------
extern "C" void kernel_launch(void* const* d_in, const int* in_sizes, int n_in,
                              void* d_out, int out_size)
{
    const float* H      = (const float*)d_in[0];
    const float* Amat   = (const float*)d_in[1];
    const float* W      = (const float*)d_in[2];
    const float* a_attn = (const float*)d_in[3];
    const float* res_W  = (const float*)d_in[4];
    const float* res_b  = (const float*)d_in[5];
    const float* gamma  = (const float*)d_in[6];
    const float* beta   = (const float*)d_in[7];
    float* out = (float*)d_out;

    void *pWh = nullptr, *pWhb = nullptr, *pR = nullptr;
    cudaGetSymbolAddress(&pWh,  g_Wh);
    cudaGetSymbolAddress(&pWhb, g_Whb);
    cudaGetSymbolAddress(&pR,   g_R);

    dim3 g1(FEAT / 128, ROWS / 128, 1);  // 8 x 64
    // Wh = H @ W  (split-bf16 3-term; fp32 + bf16 outputs)
    gemm_bf16x3<0, 1><<<g1, 256>>>(H, W, nullptr, (float*)pWh,
                                   (__nv_bfloat16*)pWhb, INF, INF, FEAT, FEAT);
    // R = H @ res_W + res_b
    gemm_bf16x3<1, 0><<<g1, 256>>>(H, res_W, res_b, (float*)pR,
                                   nullptr, INF, INF, FEAT, FEAT);

    scores_kernel<<<ROWS, 256>>>(a_attn);
    softmax_kernel<<<2 * ROWS, 256>>>(Amat, out + X_ELEMS);

    dim3 g4(1, Cc / 128, Bb * NH);
    aggr_bf16<<<g4, 256>>>();

    ln_kernel<<<ROWS, 256>>>(gamma, beta, out);
}

// round 4
// speedup vs baseline: 2.6453x; 1.0421x over previous
#include <cuda_runtime.h>
#include <cuda_bf16.h>
#include <cstdint>

// Problem constants
#define Bb 8
#define Cc 1024
#define INF 256
#define NH 8
#define OF 128
#define FEAT (NH*OF)          // 1024
#define ROWS (Bb*Cc)          // 8192
#define X_ELEMS (ROWS*FEAT)   // 8388608

// ---------------- device scratch ----
__device__ __nv_bfloat16 g_Whb[ROWS * FEAT];              // bf16 Wh (K4 B operand)
__device__ float g_R [ROWS * FEAT];                       // H@res_W + res_b
__device__ float g_Hout[ROWS * FEAT];                     // x
__device__ float g_es[ROWS * NH];
__device__ float g_ed[ROWS * NH];
__device__ __nv_bfloat16 g_alphaTb[(size_t)Bb * NH * Cc * Cc]; // (b,h,i,j) bf16

// ---------------- helpers ----
__device__ __forceinline__ void mma_bf16(float4& c, const uint32_t a[4],
                                         uint32_t b0, uint32_t b1) {
    asm volatile(
      "mma.sync.aligned.m16n8k16.row.col.f32.bf16.bf16.f32 "
      "{%0,%1,%2,%3},{%4,%5,%6,%7},{%8,%9},{%0,%1,%2,%3};"
      : "+f"(c.x), "+f"(c.y), "+f"(c.z), "+f"(c.w)
      : "r"(a[0]), "r"(a[1]), "r"(a[2]), "r"(a[3]), "r"(b0), "r"(b1));
}
__device__ __forceinline__ uint32_t packbf(float x, float y) {
    __nv_bfloat162 t;
    t.x = __float2bfloat16(x); t.y = __float2bfloat16(y);
    return *reinterpret_cast<uint32_t*>(&t);
}

// =======================================================================
// K1: split-bf16 3-term GEMM: C = A@B (+bias), near-fp32 accuracy.
// Tile 128x128, BK=16, 256 thr, double-buffered.
// MODE 0 (R gemm):  write fp32 C (+bias).
// MODE 1 (Wh gemm): write bf16 Cb only, and fuse e_src/e_dst score dots
//                   (block tile == one head's full OF) into g_es/g_ed.
// =======================================================================
#define PA 12     // A row words (8 bf16x2 + 4 pad)
#define PB 136    // B row words (128 + 8 pad)

template<int MODE>
__global__ __launch_bounds__(256) void gemm_bf16x3(
    const float* __restrict__ A, const float* __restrict__ B,
    const float* __restrict__ bias, float* __restrict__ C,
    __nv_bfloat16* __restrict__ Cb, const float* __restrict__ a_attn,
    int K, int lda, int ldb, int ldc)
{
    __shared__ uint32_t Ah[2][128 * PA];
    __shared__ uint32_t Al[2][128 * PA];
    __shared__ uint32_t Bh[2][8 * PB];
    __shared__ uint32_t Bl[2][8 * PB];
    __shared__ float sas[MODE ? 128 : 1], sad[MODE ? 128 : 1];
    __shared__ float sE[MODE ? 2 : 1][MODE ? 128 : 1];
    __shared__ float sD[MODE ? 2 : 1][MODE ? 128 : 1];

    const int tid  = threadIdx.x;
    const int m0   = blockIdx.y * 128, n0 = blockIdx.x * 128;
    const int hn   = blockIdx.x;                    // head index in MODE 1
    const int wid  = tid >> 5, lane = tid & 31;
    const int wm   = (wid & 3) * 32, wn = (wid >> 2) * 64;
    const int g    = lane >> 2, tg = lane & 3;

    if (MODE) {
        if (tid < 128)       sas[tid]       = a_attn[hn * 256 + tid];
        else                 sad[tid - 128] = a_attn[hn * 256 + 128 + (tid - 128)];
    }

    float4 acc[2][8];
#pragma unroll
    for (int mt = 0; mt < 2; mt++)
#pragma unroll
        for (int nt = 0; nt < 8; nt++) acc[mt][nt] = make_float4(0.f,0.f,0.f,0.f);

    float4 avs[2], b0v, b1v;
    const int ar = tid >> 2, as_ = tid & 3;
    const int rb = tid >> 5, cb = tid & 31;

    auto loadg = [&](int k0) {
#pragma unroll
        for (int it = 0; it < 2; it++) {
            int r = ar + it * 64;
            avs[it] = *reinterpret_cast<const float4*>(A + (size_t)(m0 + r) * lda + k0 + as_ * 4);
        }
        b0v = *reinterpret_cast<const float4*>(B + (size_t)(k0 + 2 * rb)     * ldb + n0 + cb * 4);
        b1v = *reinterpret_cast<const float4*>(B + (size_t)(k0 + 2 * rb + 1) * ldb + n0 + cb * 4);
    };
    auto stage = [&](int buf) {
#pragma unroll
        for (int it = 0; it < 2; it++) {
            int r = ar + it * 64;
            float4 v = avs[it];
            float hx = __bfloat162float(__float2bfloat16(v.x));
            float hy = __bfloat162float(__float2bfloat16(v.y));
            float hz = __bfloat162float(__float2bfloat16(v.z));
            float hw = __bfloat162float(__float2bfloat16(v.w));
            uint2 wh = make_uint2(packbf(v.x, v.y), packbf(v.z, v.w));
            uint2 wl = make_uint2(packbf(v.x - hx, v.y - hy), packbf(v.z - hz, v.w - hw));
            *reinterpret_cast<uint2*>(&Ah[buf][r * PA + as_ * 2]) = wh;
            *reinterpret_cast<uint2*>(&Al[buf][r * PA + as_ * 2]) = wl;
        }
        float p0[4] = {b0v.x, b0v.y, b0v.z, b0v.w};
        float p1[4] = {b1v.x, b1v.y, b1v.z, b1v.w};
        uint32_t wh[4], wl[4];
#pragma unroll
        for (int j = 0; j < 4; j++) {
            float h0 = __bfloat162float(__float2bfloat16(p0[j]));
            float h1 = __bfloat162float(__float2bfloat16(p1[j]));
            wh[j] = packbf(p0[j], p1[j]);
            wl[j] = packbf(p0[j] - h0, p1[j] - h1);
        }
        *reinterpret_cast<uint4*>(&Bh[buf][rb * PB + cb * 4]) = make_uint4(wh[0],wh[1],wh[2],wh[3]);
        *reinterpret_cast<uint4*>(&Bl[buf][rb * PB + cb * 4]) = make_uint4(wl[0],wl[1],wl[2],wl[3]);
    };
    auto compute = [&](int buf) {
        uint32_t ah[2][4], al[2][4];
#pragma unroll
        for (int mt = 0; mt < 2; mt++) {
            int r = wm + mt * 16 + g;
            ah[mt][0] = Ah[buf][r       * PA + tg];
            ah[mt][1] = Ah[buf][(r + 8) * PA + tg];
            ah[mt][2] = Ah[buf][r       * PA + tg + 4];
            ah[mt][3] = Ah[buf][(r + 8) * PA + tg + 4];
            al[mt][0] = Al[buf][r       * PA + tg];
            al[mt][1] = Al[buf][(r + 8) * PA + tg];
            al[mt][2] = Al[buf][r       * PA + tg + 4];
            al[mt][3] = Al[buf][(r + 8) * PA + tg + 4];
        }
#pragma unroll
        for (int nt = 0; nt < 8; nt++) {
            int cx = wn + nt * 8 + g;
            uint32_t bh0 = Bh[buf][tg       * PB + cx];
            uint32_t bh1 = Bh[buf][(tg + 4) * PB + cx];
            uint32_t bl0 = Bl[buf][tg       * PB + cx];
            uint32_t bl1 = Bl[buf][(tg + 4) * PB + cx];
#pragma unroll
            for (int mt = 0; mt < 2; mt++) {
                mma_bf16(acc[mt][nt], ah[mt], bh0, bh1);
                mma_bf16(acc[mt][nt], ah[mt], bl0, bl1);
                mma_bf16(acc[mt][nt], al[mt], bh0, bh1);
            }
        }
    };

    const int NIT = K / 16;
    loadg(0); stage(0);
    __syncthreads();
    for (int it = 0; it < NIT; it++) {
        if (it + 1 < NIT) loadg((it + 1) * 16);
        compute(it & 1);
        if (it + 1 < NIT) stage((it + 1) & 1);
        __syncthreads();
    }

    // ---- epilogue ----
#pragma unroll
    for (int mt = 0; mt < 2; mt++) {
        int r0 = m0 + wm + mt * 16 + g;
#pragma unroll
        for (int nt = 0; nt < 8; nt++) {
            int cc = n0 + wn + nt * 8 + 2 * tg;
            float4 v = acc[mt][nt];
            if (MODE == 0) {
                float bv0 = bias[cc], bv1 = bias[cc + 1];
                float2 p0 = make_float2(v.x + bv0, v.y + bv1);
                float2 p1 = make_float2(v.z + bv0, v.w + bv1);
                *reinterpret_cast<float2*>(C + (size_t)r0 * ldc + cc)       = p0;
                *reinterpret_cast<float2*>(C + (size_t)(r0 + 8) * ldc + cc) = p1;
            } else {
                __nv_bfloat162 q0, q1;
                q0.x = __float2bfloat16(v.x); q0.y = __float2bfloat16(v.y);
                q1.x = __float2bfloat16(v.z); q1.y = __float2bfloat16(v.w);
                *reinterpret_cast<__nv_bfloat162*>(Cb + (size_t)r0 * ldc + cc)       = q0;
                *reinterpret_cast<__nv_bfloat162*>(Cb + (size_t)(r0 + 8) * ldc + cc) = q1;
            }
        }
    }

    if (MODE) {
        // fused e_src/e_dst: dot each output row with a_src/a_dst for head hn
        float ps[2][2] = {{0.f,0.f},{0.f,0.f}};
        float pd[2][2] = {{0.f,0.f},{0.f,0.f}};
#pragma unroll
        for (int mt = 0; mt < 2; mt++)
#pragma unroll
            for (int nt = 0; nt < 8; nt++) {
                int c = wn + nt * 8 + 2 * tg;
                float4 v = acc[mt][nt];
                float a0 = sas[c], a1 = sas[c + 1];
                float d0 = sad[c], d1 = sad[c + 1];
                ps[mt][0] += v.x * a0 + v.y * a1;
                ps[mt][1] += v.z * a0 + v.w * a1;
                pd[mt][0] += v.x * d0 + v.y * d1;
                pd[mt][1] += v.z * d0 + v.w * d1;
            }
        // reduce over tg (4 lanes within quad)
#pragma unroll
        for (int mt = 0; mt < 2; mt++)
#pragma unroll
            for (int q = 0; q < 2; q++) {
                ps[mt][q] += __shfl_xor_sync(0xffffffffu, ps[mt][q], 1);
                ps[mt][q] += __shfl_xor_sync(0xffffffffu, ps[mt][q], 2);
                pd[mt][q] += __shfl_xor_sync(0xffffffffu, pd[mt][q], 1);
                pd[mt][q] += __shfl_xor_sync(0xffffffffu, pd[mt][q], 2);
            }
        const int wc = wid >> 2;
        if (tg == 0) {
#pragma unroll
            for (int mt = 0; mt < 2; mt++) {
                int r = wm + mt * 16 + g;
                sE[wc][r]     = ps[mt][0];
                sE[wc][r + 8] = ps[mt][1];
                sD[wc][r]     = pd[mt][0];
                sD[wc][r + 8] = pd[mt][1];
            }
        }
        __syncthreads();
        if (tid < 128) {
            g_es[(size_t)(m0 + tid) * NH + hn] = sE[0][tid] + sE[1][tid];
            g_ed[(size_t)(m0 + tid) * NH + hn] = sD[0][tid] + sD[1][tid];
        }
    }
}

// ------------------------------------- K3: softmax, register-resident
// One block per (b,i). Each thread: 4 j x 8 heads in registers.
__global__ __launch_bounds__(256) void softmax_kernel(
    const float* __restrict__ Amat, float* __restrict__ alpha_out)
{
    __shared__ float s_es[8];
    __shared__ float s_stat[8];
    __shared__ float red[8][8];
    __shared__ float s_redsum[8];
    __shared__ float s_inv;

    const int bi = blockIdx.x;
    const int b = bi >> 10, i = bi & 1023;
    const int t = threadIdx.x, wid = t >> 5, lane = t & 31;

    const float* arow = Amat + (size_t)bi * Cc;
    float av[4], psum = 0.f;
#pragma unroll
    for (int jj = 0; jj < 4; jj++) {
        int j = t + jj * 256;
        av[jj] = arow[j];
        psum += av[jj];
    }
#pragma unroll
    for (int o = 16; o; o >>= 1) psum += __shfl_xor_sync(0xffffffffu, psum, o);
    if (!lane) s_redsum[wid] = psum;
    if (t < 8) s_es[t] = g_es[(size_t)bi * NH + t];
    __syncthreads();
    if (t == 0) {
        float s = 0.f;
#pragma unroll
        for (int w = 0; w < 8; w++) s += s_redsum[w];
        s_inv = 1.0f / (s + 1e-8f);
    }
    __syncthreads();

    const float inv = s_inv;
    float es[8];
#pragma unroll
    for (int h = 0; h < 8; h++) es[h] = s_es[h];

    const float INV_T = 1.0f / 1.5f;
    float vv[4][8];
    float lmax[8];
#pragma unroll
    for (int h = 0; h < 8; h++) lmax[h] = -3.4e38f;

#pragma unroll
    for (int jj = 0; jj < 4; jj++) {
        int j = t + jj * 256;
        const float4* edp = reinterpret_cast<const float4*>(g_ed + ((size_t)b * Cc + j) * NH);
        float4 e0 = edp[0], e1 = edp[1];
        float ed[8] = {e0.x,e0.y,e0.z,e0.w,e1.x,e1.y,e1.z,e1.w};
        float aval = av[jj];
        bool mk = (aval > 0.f) || (j == i);
        float An = aval * inv;
#pragma unroll
        for (int h = 0; h < 8; h++) {
            float s = es[h] + ed[h];
            s = s > 0.f ? s : 0.2f * s;            // leaky relu
            float v = ((mk ? s : -1e9f) + An) * INV_T;
            vv[jj][h] = v;
            lmax[h] = fmaxf(lmax[h], v);
        }
    }
#pragma unroll
    for (int h = 0; h < 8; h++)
#pragma unroll
        for (int o = 16; o; o >>= 1)
            lmax[h] = fmaxf(lmax[h], __shfl_xor_sync(0xffffffffu, lmax[h], o));
    if (!lane) {
#pragma unroll
        for (int h = 0; h < 8; h++) red[wid][h] = lmax[h];
    }
    __syncthreads();
    if (t < 8) {
        float m = red[0][t];
#pragma unroll
        for (int w = 1; w < 8; w++) m = fmaxf(m, red[w][t]);
        s_stat[t] = m;
    }
    __syncthreads();
    float mh[8];
#pragma unroll
    for (int h = 0; h < 8; h++) mh[h] = s_stat[h];

    float lsum[8];
#pragma unroll
    for (int h = 0; h < 8; h++) lsum[h] = 0.f;
#pragma unroll
    for (int jj = 0; jj < 4; jj++)
#pragma unroll
        for (int h = 0; h < 8; h++) {
            float ev = __expf(vv[jj][h] - mh[h]);
            vv[jj][h] = ev;
            lsum[h] += ev;
        }
#pragma unroll
    for (int h = 0; h < 8; h++)
#pragma unroll
        for (int o = 16; o; o >>= 1)
            lsum[h] += __shfl_xor_sync(0xffffffffu, lsum[h], o);
    __syncthreads();
    if (!lane) {
#pragma unroll
        for (int h = 0; h < 8; h++) red[wid][h] = lsum[h];
    }
    __syncthreads();
    if (t < 8) {
        float s = 0.f;
#pragma unroll
        for (int w = 0; w < 8; w++) s += red[w][t];
        s_stat[t] = 1.0f / s;
    }
    __syncthreads();
    float ish[8];
#pragma unroll
    for (int h = 0; h < 8; h++) ish[h] = s_stat[h];

    // alpha (b,i,j,h) fp32 output — 32B contiguous per thread, fully coalesced
    float* oa = alpha_out + (size_t)bi * (Cc * NH);
#pragma unroll
    for (int jj = 0; jj < 4; jj++) {
        int j = t + jj * 256;
        float4 o0 = make_float4(vv[jj][0]*ish[0], vv[jj][1]*ish[1],
                                vv[jj][2]*ish[2], vv[jj][3]*ish[3]);
        float4 o1 = make_float4(vv[jj][4]*ish[4], vv[jj][5]*ish[5],
                                vv[jj][6]*ish[6], vv[jj][7]*ish[7]);
        *reinterpret_cast<float4*>(oa + (size_t)j * NH)     = o0;
        *reinterpret_cast<float4*>(oa + (size_t)j * NH + 4) = o1;
    }
    // alphaT (b,h,i,j) bf16 scratch for K4
#pragma unroll
    for (int h = 0; h < 8; h++) {
        __nv_bfloat16* ot = g_alphaTb + (((size_t)(b * NH + h)) * Cc + i) * Cc;
        float s = ish[h];
#pragma unroll
        for (int jj = 0; jj < 4; jj++) {
            int j = t + jj * 256;
            ot[j] = __float2bfloat16(vv[jj][h] * s);
        }
    }
}

// =======================================================================
// K4: bf16 mma GEMM.  per (b,h): Hout[1024,128] = alphaT@Whb + R.
// 128x128 tile (full N), BK=32, 256 thr, double-buffered.
// =======================================================================
#define PADKB 20   // words per As row (16 + 4)
#define PADNB 136  // words per Bs row (128 + 8)

__global__ __launch_bounds__(256) void aggr_bf16()
{
    __shared__ uint32_t As[2][128 * PADKB];
    __shared__ uint32_t Bs[2][16 * PADNB];

    const int z = blockIdx.z;
    const int b = z >> 3, h = z & 7;
    const __nv_bfloat16* A  = g_alphaTb + (size_t)z * Cc * Cc;
    const __nv_bfloat16* Bp = g_Whb + (size_t)b * Cc * FEAT + h * OF;
    const float* R = g_R    + (size_t)b * Cc * FEAT + h * OF;
    float*       C = g_Hout + (size_t)b * Cc * FEAT + h * OF;

    const int m0 = blockIdx.y * 128;
    const int tid = threadIdx.x;
    const int wid = tid >> 5, lane = tid & 31;
    const int wm = (wid & 3) * 32, wn = (wid >> 2) * 64;
    const int g = lane >> 2, tg = lane & 3;

    float4 acc[2][8];
#pragma unroll
    for (int mt = 0; mt < 2; mt++)
#pragma unroll
        for (int nt = 0; nt < 8; nt++) acc[mt][nt] = make_float4(0.f,0.f,0.f,0.f);

    uint4 avs[2], bv0, bv1;
    const int ar = tid >> 2, as_ = tid & 3;
    const int rb = tid >> 4, sb = tid & 15;

    auto loadg = [&](int k0) {
#pragma unroll
        for (int it = 0; it < 2; it++) {
            int r = ar + it * 64;
            avs[it] = *reinterpret_cast<const uint4*>(A + (size_t)(m0 + r) * Cc + k0 + as_ * 8);
        }
        bv0 = *reinterpret_cast<const uint4*>(Bp + (size_t)(k0 + 2 * rb)     * FEAT + sb * 8);
        bv1 = *reinterpret_cast<const uint4*>(Bp + (size_t)(k0 + 2 * rb + 1) * FEAT + sb * 8);
    };
    auto stage = [&](int buf) {
#pragma unroll
        for (int it = 0; it < 2; it++) {
            int r = ar + it * 64;
            *reinterpret_cast<uint4*>(&As[buf][r * PADKB + as_ * 4]) = avs[it];
        }
        uint32_t lo[4] = {bv0.x, bv0.y, bv0.z, bv0.w};
        uint32_t hi[4] = {bv1.x, bv1.y, bv1.z, bv1.w};
        uint32_t w[8];
#pragma unroll
        for (int j = 0; j < 4; j++) {
            w[2*j]   = (lo[j] & 0xffffu)  | (hi[j] << 16);
            w[2*j+1] = (lo[j] >> 16)      | (hi[j] & 0xffff0000u);
        }
        *reinterpret_cast<uint4*>(&Bs[buf][rb * PADNB + sb * 8])     = make_uint4(w[0],w[1],w[2],w[3]);
        *reinterpret_cast<uint4*>(&Bs[buf][rb * PADNB + sb * 8 + 4]) = make_uint4(w[4],w[5],w[6],w[7]);
    };
    auto compute = [&](int buf) {
#pragma unroll
        for (int kk2 = 0; kk2 < 16; kk2 += 8) {
            uint32_t af[2][4];
#pragma unroll
            for (int mt = 0; mt < 2; mt++) {
                int r = wm + mt * 16 + g;
                af[mt][0] = As[buf][r       * PADKB + kk2 + tg];
                af[mt][1] = As[buf][(r + 8) * PADKB + kk2 + tg];
                af[mt][2] = As[buf][r       * PADKB + kk2 + tg + 4];
                af[mt][3] = As[buf][(r + 8) * PADKB + kk2 + tg + 4];
            }
#pragma unroll
            for (int nt = 0; nt < 8; nt++) {
                int cx = wn + nt * 8 + g;
                uint32_t b0 = Bs[buf][(kk2 + tg)     * PADNB + cx];
                uint32_t b1 = Bs[buf][(kk2 + tg + 4) * PADNB + cx];
#pragma unroll
                for (int mt = 0; mt < 2; mt++) mma_bf16(acc[mt][nt], af[mt], b0, b1);
            }
        }
    };

    const int NIT = Cc / 32;   // 32
    loadg(0); stage(0);
    __syncthreads();
    for (int it = 0; it < NIT; it++) {
        if (it + 1 < NIT) loadg((it + 1) * 32);
        compute(it & 1);
        if (it + 1 < NIT) stage((it + 1) & 1);
        __syncthreads();
    }

#pragma unroll
    for (int mt = 0; mt < 2; mt++) {
        int r0 = m0 + wm + mt * 16 + g;
#pragma unroll
        for (int nt = 0; nt < 8; nt++) {
            int cc = wn + nt * 8 + 2 * tg;
            float4 v = acc[mt][nt];
            float2 ra = *reinterpret_cast<const float2*>(R + (size_t)r0 * FEAT + cc);
            float2 rbv = *reinterpret_cast<const float2*>(R + (size_t)(r0 + 8) * FEAT + cc);
            float2 p0 = make_float2(v.x + ra.x,  v.y + ra.y);
            float2 p1 = make_float2(v.z + rbv.x, v.w + rbv.y);
            *reinterpret_cast<float2*>(C + (size_t)r0 * FEAT + cc)       = p0;
            *reinterpret_cast<float2*>(C + (size_t)(r0 + 8) * FEAT + cc) = p1;
        }
    }
}

// ------------------------------------------------- K5: LayerNorm + ReLU ----
__global__ __launch_bounds__(256) void ln_kernel(
    const float* __restrict__ gamma, const float* __restrict__ beta,
    float* __restrict__ out)
{
    __shared__ float rs[8], rs2[8];
    __shared__ float s_mu, s_rstd;
    const int bi = blockIdx.x;
    const int t = threadIdx.x, wid = t >> 5, lane = t & 31;
    const float* x = g_Hout + (size_t)bi * FEAT;
    float xs[4], s = 0.f, s2 = 0.f;
#pragma unroll
    for (int jj = 0; jj < 4; jj++) {
        float v = x[t + jj * 256];
        xs[jj] = v; s += v; s2 += v * v;
    }
#pragma unroll
    for (int o = 16; o; o >>= 1) {
        s  += __shfl_xor_sync(0xffffffffu, s, o);
        s2 += __shfl_xor_sync(0xffffffffu, s2, o);
    }
    if (!lane) { rs[wid] = s; rs2[wid] = s2; }
    __syncthreads();
    if (t == 0) {
        float ts = 0.f, ts2 = 0.f;
#pragma unroll
        for (int w = 0; w < 8; w++) { ts += rs[w]; ts2 += rs2[w]; }
        float mu = ts * (1.0f / FEAT);
        float var = ts2 * (1.0f / FEAT) - mu * mu;
        s_mu = mu;
        s_rstd = rsqrtf(var + 1e-5f);
    }
    __syncthreads();
    const float mu = s_mu, rstd = s_rstd;
#pragma unroll
    for (int jj = 0; jj < 4; jj++) {
        int f = t + jj * 256;
        float y = (xs[jj] - mu) * rstd * gamma[f] + beta[f];
        out[(size_t)bi * FEAT + f] = fmaxf(y, 0.f);
    }
}

// --------------------------------------------------------------------------
extern "C" void kernel_launch(void* const* d_in, const int* in_sizes, int n_in,
                              void* d_out, int out_size)
{
    const float* H      = (const float*)d_in[0];
    const float* Amat   = (const float*)d_in[1];
    const float* W      = (const float*)d_in[2];
    const float* a_attn = (const float*)d_in[3];
    const float* res_W  = (const float*)d_in[4];
    const float* res_b  = (const float*)d_in[5];
    const float* gamma  = (const float*)d_in[6];
    const float* beta   = (const float*)d_in[7];
    float* out = (float*)d_out;

    void *pWhb = nullptr, *pR = nullptr;
    cudaGetSymbolAddress(&pWhb, g_Whb);
    cudaGetSymbolAddress(&pR,   g_R);

    dim3 g1(FEAT / 128, ROWS / 128, 1);  // 8 x 64
    // Wh (bf16 out) + fused e_src/e_dst scores
    gemm_bf16x3<1><<<g1, 256>>>(H, W, nullptr, nullptr,
                                (__nv_bfloat16*)pWhb, a_attn, INF, INF, FEAT, FEAT);
    // R = H @ res_W + res_b (fp32 out)
    gemm_bf16x3<0><<<g1, 256>>>(H, res_W, res_b, (float*)pR,
                                nullptr, nullptr, INF, INF, FEAT, FEAT);

    softmax_kernel<<<ROWS, 256>>>(Amat, out + X_ELEMS);

    dim3 g4(1, Cc / 128, Bb * NH);
    aggr_bf16<<<g4, 256>>>();

    ln_kernel<<<ROWS, 256>>>(gamma, beta, out);
}

// round 5
// speedup vs baseline: 3.0947x; 1.1699x over previous
#include <cuda_runtime.h>
#include <cuda_bf16.h>
#include <cstdint>

// Problem constants
#define Bb 8
#define Cc 1024
#define INF 256
#define NH 8
#define OF 128
#define FEAT (NH*OF)          // 1024
#define ROWS (Bb*Cc)          // 8192
#define X_ELEMS (ROWS*FEAT)   // 8388608

// ---------------- device scratch ----
__device__ __nv_bfloat16 g_Whb[ROWS * FEAT];              // bf16 Wh (K4 B operand)
__device__ float g_R [ROWS * FEAT];                       // H@res_W + res_b
__device__ float g_Hout[ROWS * FEAT];                     // x
__device__ float g_es[ROWS * NH];
__device__ float g_ed[ROWS * NH];
__device__ __nv_bfloat16 g_alphaTb[(size_t)Bb * NH * Cc * Cc]; // (b,h,i,j) bf16

// ---------------- helpers ----
__device__ __forceinline__ void mma_bf16(float4& c, const uint32_t a[4],
                                         uint32_t b0, uint32_t b1) {
    asm volatile(
      "mma.sync.aligned.m16n8k16.row.col.f32.bf16.bf16.f32 "
      "{%0,%1,%2,%3},{%4,%5,%6,%7},{%8,%9},{%0,%1,%2,%3};"
      : "+f"(c.x), "+f"(c.y), "+f"(c.z), "+f"(c.w)
      : "r"(a[0]), "r"(a[1]), "r"(a[2]), "r"(a[3]), "r"(b0), "r"(b1));
}
__device__ __forceinline__ uint32_t packbf(float x, float y) {
    __nv_bfloat162 t;
    t.x = __float2bfloat16(x); t.y = __float2bfloat16(y);
    return *reinterpret_cast<uint32_t*>(&t);
}
#define CP16(dst, src) \
    asm volatile("cp.async.cg.shared.global [%0], [%1], 16;" :: "r"(dst), "l"(src))
#define CP_COMMIT() asm volatile("cp.async.commit_group;")
#define CP_WAIT(N)  asm volatile("cp.async.wait_group %0;" :: "n"(N))
#define LDSM_X4(r, addr) \
    asm volatile("ldmatrix.sync.aligned.m8n8.x4.shared.b16 {%0,%1,%2,%3}, [%4];" \
      : "=r"((r)[0]), "=r"((r)[1]), "=r"((r)[2]), "=r"((r)[3]) : "r"(addr))
#define LDSM_X4T(r, addr) \
    asm volatile("ldmatrix.sync.aligned.m8n8.x4.trans.shared.b16 {%0,%1,%2,%3}, [%4];" \
      : "=r"((r)[0]), "=r"((r)[1]), "=r"((r)[2]), "=r"((r)[3]) : "r"(addr))

// =======================================================================
// K1: split-bf16 3-term GEMM (merged Wh + R launches via blockIdx.z).
// mode 0: Cb(bf16) = H@W, plus fused e_src/e_dst scores.
// mode 1: C(fp32)  = H@res_W + res_b.
// Tile 128x128, BK=16, 256 thr, double-buffered.
// =======================================================================
#define PA 12     // A row words (8 bf16x2 + 4 pad)
#define PB 136    // B row words (128 + 8 pad)

__global__ __launch_bounds__(256) void dual_gemm(
    const float* __restrict__ A, const float* __restrict__ B0,
    const float* __restrict__ B1, const float* __restrict__ bias,
    __nv_bfloat16* __restrict__ Cb, float* __restrict__ C,
    const float* __restrict__ a_attn)
{
    __shared__ uint32_t Ah[2][128 * PA];
    __shared__ uint32_t Al[2][128 * PA];
    __shared__ uint32_t Bh[2][8 * PB];
    __shared__ uint32_t Bl[2][8 * PB];
    __shared__ float sas[128], sad[128];
    __shared__ float sE[2][128];
    __shared__ float sD[2][128];

    const int mode = blockIdx.z;
    const float* __restrict__ B = mode ? B1 : B0;
    const int K = INF, lda = INF, ldb = FEAT, ldc = FEAT;

    const int tid  = threadIdx.x;
    const int m0   = blockIdx.y * 128, n0 = blockIdx.x * 128;
    const int hn   = blockIdx.x;
    const int wid  = tid >> 5, lane = tid & 31;
    const int wm   = (wid & 3) * 32, wn = (wid >> 2) * 64;
    const int g    = lane >> 2, tg = lane & 3;

    if (mode == 0) {
        if (tid < 128)       sas[tid]       = a_attn[hn * 256 + tid];
        else                 sad[tid - 128] = a_attn[hn * 256 + 128 + (tid - 128)];
    }

    float4 acc[2][8];
#pragma unroll
    for (int mt = 0; mt < 2; mt++)
#pragma unroll
        for (int nt = 0; nt < 8; nt++) acc[mt][nt] = make_float4(0.f,0.f,0.f,0.f);

    float4 avs[2], b0v, b1v;
    const int ar = tid >> 2, as_ = tid & 3;
    const int rb = tid >> 5, cb = tid & 31;

    auto loadg = [&](int k0) {
#pragma unroll
        for (int it = 0; it < 2; it++) {
            int r = ar + it * 64;
            avs[it] = *reinterpret_cast<const float4*>(A + (size_t)(m0 + r) * lda + k0 + as_ * 4);
        }
        b0v = *reinterpret_cast<const float4*>(B + (size_t)(k0 + 2 * rb)     * ldb + n0 + cb * 4);
        b1v = *reinterpret_cast<const float4*>(B + (size_t)(k0 + 2 * rb + 1) * ldb + n0 + cb * 4);
    };
    auto stage = [&](int buf) {
#pragma unroll
        for (int it = 0; it < 2; it++) {
            int r = ar + it * 64;
            float4 v = avs[it];
            float hx = __bfloat162float(__float2bfloat16(v.x));
            float hy = __bfloat162float(__float2bfloat16(v.y));
            float hz = __bfloat162float(__float2bfloat16(v.z));
            float hw = __bfloat162float(__float2bfloat16(v.w));
            uint2 wh = make_uint2(packbf(v.x, v.y), packbf(v.z, v.w));
            uint2 wl = make_uint2(packbf(v.x - hx, v.y - hy), packbf(v.z - hz, v.w - hw));
            *reinterpret_cast<uint2*>(&Ah[buf][r * PA + as_ * 2]) = wh;
            *reinterpret_cast<uint2*>(&Al[buf][r * PA + as_ * 2]) = wl;
        }
        float p0[4] = {b0v.x, b0v.y, b0v.z, b0v.w};
        float p1[4] = {b1v.x, b1v.y, b1v.z, b1v.w};
        uint32_t wh[4], wl[4];
#pragma unroll
        for (int j = 0; j < 4; j++) {
            float h0 = __bfloat162float(__float2bfloat16(p0[j]));
            float h1 = __bfloat162float(__float2bfloat16(p1[j]));
            wh[j] = packbf(p0[j], p1[j]);
            wl[j] = packbf(p0[j] - h0, p1[j] - h1);
        }
        *reinterpret_cast<uint4*>(&Bh[buf][rb * PB + cb * 4]) = make_uint4(wh[0],wh[1],wh[2],wh[3]);
        *reinterpret_cast<uint4*>(&Bl[buf][rb * PB + cb * 4]) = make_uint4(wl[0],wl[1],wl[2],wl[3]);
    };
    auto compute = [&](int buf) {
        uint32_t ah[2][4], al[2][4];
#pragma unroll
        for (int mt = 0; mt < 2; mt++) {
            int r = wm + mt * 16 + g;
            ah[mt][0] = Ah[buf][r       * PA + tg];
            ah[mt][1] = Ah[buf][(r + 8) * PA + tg];
            ah[mt][2] = Ah[buf][r       * PA + tg + 4];
            ah[mt][3] = Ah[buf][(r + 8) * PA + tg + 4];
            al[mt][0] = Al[buf][r       * PA + tg];
            al[mt][1] = Al[buf][(r + 8) * PA + tg];
            al[mt][2] = Al[buf][r       * PA + tg + 4];
            al[mt][3] = Al[buf][(r + 8) * PA + tg + 4];
        }
#pragma unroll
        for (int nt = 0; nt < 8; nt++) {
            int cx = wn + nt * 8 + g;
            uint32_t bh0 = Bh[buf][tg       * PB + cx];
            uint32_t bh1 = Bh[buf][(tg + 4) * PB + cx];
            uint32_t bl0 = Bl[buf][tg       * PB + cx];
            uint32_t bl1 = Bl[buf][(tg + 4) * PB + cx];
#pragma unroll
            for (int mt = 0; mt < 2; mt++) {
                mma_bf16(acc[mt][nt], ah[mt], bh0, bh1);
                mma_bf16(acc[mt][nt], ah[mt], bl0, bl1);
                mma_bf16(acc[mt][nt], al[mt], bh0, bh1);
            }
        }
    };

    const int NIT = K / 16;
    loadg(0); stage(0);
    __syncthreads();
    for (int it = 0; it < NIT; it++) {
        if (it + 1 < NIT) loadg((it + 1) * 16);
        compute(it & 1);
        if (it + 1 < NIT) stage((it + 1) & 1);
        __syncthreads();
    }

    // ---- epilogue ----
#pragma unroll
    for (int mt = 0; mt < 2; mt++) {
        int r0 = m0 + wm + mt * 16 + g;
#pragma unroll
        for (int nt = 0; nt < 8; nt++) {
            int cc = n0 + wn + nt * 8 + 2 * tg;
            float4 v = acc[mt][nt];
            if (mode) {
                float bv0 = bias[cc], bv1 = bias[cc + 1];
                float2 p0 = make_float2(v.x + bv0, v.y + bv1);
                float2 p1 = make_float2(v.z + bv0, v.w + bv1);
                *reinterpret_cast<float2*>(C + (size_t)r0 * ldc + cc)       = p0;
                *reinterpret_cast<float2*>(C + (size_t)(r0 + 8) * ldc + cc) = p1;
            } else {
                __nv_bfloat162 q0, q1;
                q0.x = __float2bfloat16(v.x); q0.y = __float2bfloat16(v.y);
                q1.x = __float2bfloat16(v.z); q1.y = __float2bfloat16(v.w);
                *reinterpret_cast<__nv_bfloat162*>(Cb + (size_t)r0 * ldc + cc)       = q0;
                *reinterpret_cast<__nv_bfloat162*>(Cb + (size_t)(r0 + 8) * ldc + cc) = q1;
            }
        }
    }

    if (mode == 0) {
        float ps[2][2] = {{0.f,0.f},{0.f,0.f}};
        float pd[2][2] = {{0.f,0.f},{0.f,0.f}};
#pragma unroll
        for (int mt = 0; mt < 2; mt++)
#pragma unroll
            for (int nt = 0; nt < 8; nt++) {
                int c = wn + nt * 8 + 2 * tg;
                float4 v = acc[mt][nt];
                float a0 = sas[c], a1 = sas[c + 1];
                float d0 = sad[c], d1 = sad[c + 1];
                ps[mt][0] += v.x * a0 + v.y * a1;
                ps[mt][1] += v.z * a0 + v.w * a1;
                pd[mt][0] += v.x * d0 + v.y * d1;
                pd[mt][1] += v.z * d0 + v.w * d1;
            }
#pragma unroll
        for (int mt = 0; mt < 2; mt++)
#pragma unroll
            for (int q = 0; q < 2; q++) {
                ps[mt][q] += __shfl_xor_sync(0xffffffffu, ps[mt][q], 1);
                ps[mt][q] += __shfl_xor_sync(0xffffffffu, ps[mt][q], 2);
                pd[mt][q] += __shfl_xor_sync(0xffffffffu, pd[mt][q], 1);
                pd[mt][q] += __shfl_xor_sync(0xffffffffu, pd[mt][q], 2);
            }
        const int wc = wid >> 2;
        if (tg == 0) {
#pragma unroll
            for (int mt = 0; mt < 2; mt++) {
                int r = wm + mt * 16 + g;
                sE[wc][r]     = ps[mt][0];
                sE[wc][r + 8] = ps[mt][1];
                sD[wc][r]     = pd[mt][0];
                sD[wc][r + 8] = pd[mt][1];
            }
        }
        __syncthreads();
        if (tid < 128) {
            g_es[(size_t)(m0 + tid) * NH + hn] = sE[0][tid] + sE[1][tid];
            g_ed[(size_t)(m0 + tid) * NH + hn] = sD[0][tid] + sD[1][tid];
        }
    }
}

// ------------------------------------- K3: softmax, register-resident
__global__ __launch_bounds__(256) void softmax_kernel(
    const float* __restrict__ Amat, float* __restrict__ alpha_out)
{
    __shared__ float s_es[8];
    __shared__ float s_stat[8];
    __shared__ float red[8][8];
    __shared__ float s_redsum[8];
    __shared__ float s_inv;

    const int bi = blockIdx.x;
    const int b = bi >> 10, i = bi & 1023;
    const int t = threadIdx.x, wid = t >> 5, lane = t & 31;

    const float* arow = Amat + (size_t)bi * Cc;
    float av[4], psum = 0.f;
#pragma unroll
    for (int jj = 0; jj < 4; jj++) {
        int j = t + jj * 256;
        av[jj] = arow[j];
        psum += av[jj];
    }
#pragma unroll
    for (int o = 16; o; o >>= 1) psum += __shfl_xor_sync(0xffffffffu, psum, o);
    if (!lane) s_redsum[wid] = psum;
    if (t < 8) s_es[t] = g_es[(size_t)bi * NH + t];
    __syncthreads();
    if (t == 0) {
        float s = 0.f;
#pragma unroll
        for (int w = 0; w < 8; w++) s += s_redsum[w];
        s_inv = 1.0f / (s + 1e-8f);
    }
    __syncthreads();

    const float inv = s_inv;
    float es[8];
#pragma unroll
    for (int h = 0; h < 8; h++) es[h] = s_es[h];

    const float INV_T = 1.0f / 1.5f;
    float vv[4][8];
    float lmax[8];
#pragma unroll
    for (int h = 0; h < 8; h++) lmax[h] = -3.4e38f;

#pragma unroll
    for (int jj = 0; jj < 4; jj++) {
        int j = t + jj * 256;
        const float4* edp = reinterpret_cast<const float4*>(g_ed + ((size_t)b * Cc + j) * NH);
        float4 e0 = edp[0], e1 = edp[1];
        float ed[8] = {e0.x,e0.y,e0.z,e0.w,e1.x,e1.y,e1.z,e1.w};
        float aval = av[jj];
        bool mk = (aval > 0.f) || (j == i);
        float An = aval * inv;
#pragma unroll
        for (int h = 0; h < 8; h++) {
            float s = es[h] + ed[h];
            s = s > 0.f ? s : 0.2f * s;
            float v = ((mk ? s : -1e9f) + An) * INV_T;
            vv[jj][h] = v;
            lmax[h] = fmaxf(lmax[h], v);
        }
    }
#pragma unroll
    for (int h = 0; h < 8; h++)
#pragma unroll
        for (int o = 16; o; o >>= 1)
            lmax[h] = fmaxf(lmax[h], __shfl_xor_sync(0xffffffffu, lmax[h], o));
    if (!lane) {
#pragma unroll
        for (int h = 0; h < 8; h++) red[wid][h] = lmax[h];
    }
    __syncthreads();
    if (t < 8) {
        float m = red[0][t];
#pragma unroll
        for (int w = 1; w < 8; w++) m = fmaxf(m, red[w][t]);
        s_stat[t] = m;
    }
    __syncthreads();
    float mh[8];
#pragma unroll
    for (int h = 0; h < 8; h++) mh[h] = s_stat[h];

    float lsum[8];
#pragma unroll
    for (int h = 0; h < 8; h++) lsum[h] = 0.f;
#pragma unroll
    for (int jj = 0; jj < 4; jj++)
#pragma unroll
        for (int h = 0; h < 8; h++) {
            float ev = __expf(vv[jj][h] - mh[h]);
            vv[jj][h] = ev;
            lsum[h] += ev;
        }
#pragma unroll
    for (int h = 0; h < 8; h++)
#pragma unroll
        for (int o = 16; o; o >>= 1)
            lsum[h] += __shfl_xor_sync(0xffffffffu, lsum[h], o);
    __syncthreads();
    if (!lane) {
#pragma unroll
        for (int h = 0; h < 8; h++) red[wid][h] = lsum[h];
    }
    __syncthreads();
    if (t < 8) {
        float s = 0.f;
#pragma unroll
        for (int w = 0; w < 8; w++) s += red[w][t];
        s_stat[t] = 1.0f / s;
    }
    __syncthreads();
    float ish[8];
#pragma unroll
    for (int h = 0; h < 8; h++) ish[h] = s_stat[h];

    float* oa = alpha_out + (size_t)bi * (Cc * NH);
#pragma unroll
    for (int jj = 0; jj < 4; jj++) {
        int j = t + jj * 256;
        float4 o0 = make_float4(vv[jj][0]*ish[0], vv[jj][1]*ish[1],
                                vv[jj][2]*ish[2], vv[jj][3]*ish[3]);
        float4 o1 = make_float4(vv[jj][4]*ish[4], vv[jj][5]*ish[5],
                                vv[jj][6]*ish[6], vv[jj][7]*ish[7]);
        *reinterpret_cast<float4*>(oa + (size_t)j * NH)     = o0;
        *reinterpret_cast<float4*>(oa + (size_t)j * NH + 4) = o1;
    }
#pragma unroll
    for (int h = 0; h < 8; h++) {
        __nv_bfloat16* ot = g_alphaTb + (((size_t)(b * NH + h)) * Cc + i) * Cc;
        float s = ish[h];
#pragma unroll
        for (int jj = 0; jj < 4; jj++) {
            int j = t + jj * 256;
            ot[j] = __float2bfloat16(vv[jj][h] * s);
        }
    }
}

// =======================================================================
// K4: aggr GEMM v2. per (b,h): Hout[1024,128] = alphaT@Whb + R.
// 128x128 tile, BK=32, 256 thr, 3-stage cp.async + ldmatrix.
// =======================================================================
#define PAS 20                 // A row stride (words): 16 used + 4 pad (80B)
#define PBS 68                 // B row stride (words): 64 used + 4 pad (272B)
#define A_STG (128 * PAS)      // 2560 words / stage
#define B_STG (32 * PBS)       // 2176 words / stage
#define AGGR_SMEM (3 * (A_STG + B_STG) * 4)   // 56832 bytes

__global__ __launch_bounds__(256, 2) void aggr_bf16()
{
    extern __shared__ uint32_t smem_u[];
    const int z = blockIdx.z;
    const int b = z >> 3, h = z & 7;
    const __nv_bfloat16* __restrict__ A  = g_alphaTb + (size_t)z * Cc * Cc;
    const __nv_bfloat16* __restrict__ Bp = g_Whb + (size_t)b * Cc * FEAT + h * OF;
    const float* __restrict__ R = g_R    + (size_t)b * Cc * FEAT + h * OF;
    float*       __restrict__ C = g_Hout + (size_t)b * Cc * FEAT + h * OF;

    const int m0 = blockIdx.y * 128;
    const int tid = threadIdx.x;
    const int wid = tid >> 5, lane = tid & 31;
    const int wm = (wid & 3) * 32, wn = (wid >> 2) * 64;
    const int g = lane >> 2, tg = lane & 3;

    uint32_t sbase;
    {
        void* p = smem_u;
        sbase = (uint32_t)__cvta_generic_to_shared(p);
    }
    const uint32_t aBase = sbase;                       // bytes
    const uint32_t bBase = sbase + 3 * A_STG * 4;

    float4 acc[2][8];
#pragma unroll
    for (int mt = 0; mt < 2; mt++)
#pragma unroll
        for (int nt = 0; nt < 8; nt++) acc[mt][nt] = make_float4(0.f,0.f,0.f,0.f);

    auto issue = [&](int slot, int k0) {
#pragma unroll
        for (int i = 0; i < 2; i++) {
            int c = tid + i * 256;                      // 0..511
            int r = c >> 2, seg = c & 3;
            const __nv_bfloat16* src = A + (size_t)(m0 + r) * Cc + k0 + seg * 8;
            uint32_t dst = aBase + (slot * A_STG + r * PAS + seg * 4) * 4;
            CP16(dst, src);
        }
#pragma unroll
        for (int i = 0; i < 2; i++) {
            int c = tid + i * 256;
            int kr = c >> 4, seg = c & 15;
            const __nv_bfloat16* src = Bp + (size_t)(k0 + kr) * FEAT + seg * 8;
            uint32_t dst = bBase + (slot * B_STG + kr * PBS + seg * 4) * 4;
            CP16(dst, src);
        }
        CP_COMMIT();
    };

    auto compute = [&](int slot) {
        const uint32_t aw = aBase + slot * A_STG * 4;
        const uint32_t bw = bBase + slot * B_STG * 4;
        const int mtx = lane >> 3;                      // matrix id 0..3
        const int mr  = lane & 7;
#pragma unroll
        for (int kk2 = 0; kk2 < 2; kk2++) {
            uint32_t af[2][4];
#pragma unroll
            for (int mt = 0; mt < 2; mt++) {
                int row = wm + mt * 16 + (mtx & 1) * 8 + mr;
                int col = kk2 * 8 + (mtx >> 1) * 4;
                LDSM_X4(af[mt], aw + (row * PAS + col) * 4);
            }
#pragma unroll
            for (int p = 0; p < 4; p++) {
                uint32_t bf[4];
                int kr = kk2 * 16 + (mtx & 1) * 8 + mr;
                int nb = wn + p * 16 + (mtx >> 1) * 8;  // bf16 col
                LDSM_X4T(bf, bw + (kr * PBS + (nb >> 1)) * 4);
#pragma unroll
                for (int mt = 0; mt < 2; mt++) {
                    mma_bf16(acc[mt][2 * p],     af[mt], bf[0], bf[1]);
                    mma_bf16(acc[mt][2 * p + 1], af[mt], bf[2], bf[3]);
                }
            }
        }
    };

    const int NIT = Cc / 32;                            // 32
    issue(0, 0);
    issue(1, 32);
    for (int it = 0; it < NIT; it++) {
        if (it + 2 < NIT) { CP_WAIT(1); } else { CP_WAIT(0); }
        __syncthreads();
        if (it + 2 < NIT) issue((it + 2) % 3, (it + 2) * 32);
        compute(it % 3);
    }

#pragma unroll
    for (int mt = 0; mt < 2; mt++) {
        int r0 = m0 + wm + mt * 16 + g;
#pragma unroll
        for (int nt = 0; nt < 8; nt++) {
            int cc = wn + nt * 8 + 2 * tg;
            float4 v = acc[mt][nt];
            float2 ra  = *reinterpret_cast<const float2*>(R + (size_t)r0 * FEAT + cc);
            float2 rbv = *reinterpret_cast<const float2*>(R + (size_t)(r0 + 8) * FEAT + cc);
            float2 p0 = make_float2(v.x + ra.x,  v.y + ra.y);
            float2 p1 = make_float2(v.z + rbv.x, v.w + rbv.y);
            *reinterpret_cast<float2*>(C + (size_t)r0 * FEAT + cc)       = p0;
            *reinterpret_cast<float2*>(C + (size_t)(r0 + 8) * FEAT + cc) = p1;
        }
    }
}

// ------------------------------------------------- K5: LayerNorm + ReLU ----
__global__ __launch_bounds__(256) void ln_kernel(
    const float* __restrict__ gamma, const float* __restrict__ beta,
    float* __restrict__ out)
{
    __shared__ float rs[8], rs2[8];
    __shared__ float s_mu, s_rstd;
    const int bi = blockIdx.x;
    const int t = threadIdx.x, wid = t >> 5, lane = t & 31;
    const float* x = g_Hout + (size_t)bi * FEAT;
    float xs[4], s = 0.f, s2 = 0.f;
#pragma unroll
    for (int jj = 0; jj < 4; jj++) {
        float v = x[t + jj * 256];
        xs[jj] = v; s += v; s2 += v * v;
    }
#pragma unroll
    for (int o = 16; o; o >>= 1) {
        s  += __shfl_xor_sync(0xffffffffu, s, o);
        s2 += __shfl_xor_sync(0xffffffffu, s2, o);
    }
    if (!lane) { rs[wid] = s; rs2[wid] = s2; }
    __syncthreads();
    if (t == 0) {
        float ts = 0.f, ts2 = 0.f;
#pragma unroll
        for (int w = 0; w < 8; w++) { ts += rs[w]; ts2 += rs2[w]; }
        float mu = ts * (1.0f / FEAT);
        float var = ts2 * (1.0f / FEAT) - mu * mu;
        s_mu = mu;
        s_rstd = rsqrtf(var + 1e-5f);
    }
    __syncthreads();
    const float mu = s_mu, rstd = s_rstd;
#pragma unroll
    for (int jj = 0; jj < 4; jj++) {
        int f = t + jj * 256;
        float y = (xs[jj] - mu) * rstd * gamma[f] + beta[f];
        out[(size_t)bi * FEAT + f] = fmaxf(y, 0.f);
    }
}

// --------------------------------------------------------------------------
extern "C" void kernel_launch(void* const* d_in, const int* in_sizes, int n_in,
                              void* d_out, int out_size)
{
    const float* H      = (const float*)d_in[0];
    const float* Amat   = (const float*)d_in[1];
    const float* W      = (const float*)d_in[2];
    const float* a_attn = (const float*)d_in[3];
    const float* res_W  = (const float*)d_in[4];
    const float* res_b  = (const float*)d_in[5];
    const float* gamma  = (const float*)d_in[6];
    const float* beta   = (const float*)d_in[7];
    float* out = (float*)d_out;

    void *pWhb = nullptr, *pR = nullptr;
    cudaGetSymbolAddress(&pWhb, g_Whb);
    cudaGetSymbolAddress(&pR,   g_R);

    // K1: merged Wh(+scores) and R GEMMs
    dim3 g1(FEAT / 128, ROWS / 128, 2);  // 8 x 64 x 2
    dual_gemm<<<g1, 256>>>(H, W, res_W, res_b,
                           (__nv_bfloat16*)pWhb, (float*)pR, a_attn);

    softmax_kernel<<<ROWS, 256>>>(Amat, out + X_ELEMS);

    // K4: 3-stage cp.async + ldmatrix aggregation GEMM
    static bool smem_set = false;
    if (!smem_set) {
        cudaFuncSetAttribute(aggr_bf16,
            cudaFuncAttributeMaxDynamicSharedMemorySize, AGGR_SMEM);
        smem_set = true;
    }
    dim3 g4(1, Cc / 128, Bb * NH);
    aggr_bf16<<<g4, 256, AGGR_SMEM>>>();

    ln_kernel<<<ROWS, 256>>>(gamma, beta, out);
}

// round 6
// speedup vs baseline: 3.3180x; 1.0721x over previous
#include <cuda_runtime.h>
#include <cuda_bf16.h>
#include <cstdint>

// Problem constants
#define Bb 8
#define Cc 1024
#define INF 256
#define NH 8
#define OF 128
#define FEAT (NH*OF)          // 1024
#define ROWS (Bb*Cc)          // 8192
#define X_ELEMS (ROWS*FEAT)   // 8388608
#define H_ELE (ROWS*INF)      // 2097152
#define W_ELE (INF*FEAT)      // 262144

// ---------------- device scratch ----
__device__ __nv_bfloat16 g_Whb[ROWS * FEAT];              // bf16 Wh (aggr B operand)
__device__ float g_R [ROWS * FEAT];                       // H@res_W + res_b
__device__ float g_Hout[ROWS * FEAT];                     // x
__device__ float g_es[ROWS * NH];
__device__ float g_ed[ROWS * NH];
__device__ __nv_bfloat16 g_alphaTb[(size_t)Bb * NH * Cc * Cc]; // (b,h,i,j) bf16
// split-bf16 operands (prep kernel fills these)
__device__ __nv_bfloat16 g_Hh[H_ELE], g_Hl[H_ELE];
__device__ __nv_bfloat16 g_B0h[W_ELE], g_B0l[W_ELE];      // W hi/lo
__device__ __nv_bfloat16 g_B1h[W_ELE], g_B1l[W_ELE];      // res_W hi/lo

// ---------------- helpers ----
__device__ __forceinline__ void mma_bf16(float4& c, const uint32_t a[4],
                                         uint32_t b0, uint32_t b1) {
    asm volatile(
      "mma.sync.aligned.m16n8k16.row.col.f32.bf16.bf16.f32 "
      "{%0,%1,%2,%3},{%4,%5,%6,%7},{%8,%9},{%0,%1,%2,%3};"
      : "+f"(c.x), "+f"(c.y), "+f"(c.z), "+f"(c.w)
      : "r"(a[0]), "r"(a[1]), "r"(a[2]), "r"(a[3]), "r"(b0), "r"(b1));
}
__device__ __forceinline__ uint32_t packbf(float x, float y) {
    __nv_bfloat162 t;
    t.x = __float2bfloat16(x); t.y = __float2bfloat16(y);
    return *reinterpret_cast<uint32_t*>(&t);
}
#define CP16(dst, src) \
    asm volatile("cp.async.cg.shared.global [%0], [%1], 16;" :: "r"(dst), "l"(src))
#define CP_COMMIT() asm volatile("cp.async.commit_group;")
#define CP_WAIT(N)  asm volatile("cp.async.wait_group %0;" :: "n"(N))
#define LDSM_X4(r, addr) \
    asm volatile("ldmatrix.sync.aligned.m8n8.x4.shared.b16 {%0,%1,%2,%3}, [%4];" \
      : "=r"((r)[0]), "=r"((r)[1]), "=r"((r)[2]), "=r"((r)[3]) : "r"(addr))
#define LDSM_X4T(r, addr) \
    asm volatile("ldmatrix.sync.aligned.m8n8.x4.trans.shared.b16 {%0,%1,%2,%3}, [%4];" \
      : "=r"((r)[0]), "=r"((r)[1]), "=r"((r)[2]), "=r"((r)[3]) : "r"(addr))

// =======================================================================
// K0: prep — split fp32 operands into bf16 hi/lo pairs.
// =======================================================================
__global__ __launch_bounds__(256) void prep_kernel(
    const float* __restrict__ H, const float* __restrict__ W,
    const float* __restrict__ rW)
{
    const int idx = blockIdx.x * 256 + threadIdx.x;     // one float4 each
    const int nH = H_ELE / 4, nW = W_ELE / 4;
    const float* src; __nv_bfloat16 *dh, *dl; int off;
    if (idx < nH)            { src = H;  dh = g_Hh;  dl = g_Hl;  off = idx; }
    else if (idx < nH + nW)  { src = W;  dh = g_B0h; dl = g_B0l; off = idx - nH; }
    else if (idx < nH + 2*nW){ src = rW; dh = g_B1h; dl = g_B1l; off = idx - nH - nW; }
    else return;
    float4 v = reinterpret_cast<const float4*>(src)[off];
    float hx = __bfloat162float(__float2bfloat16(v.x));
    float hy = __bfloat162float(__float2bfloat16(v.y));
    float hz = __bfloat162float(__float2bfloat16(v.z));
    float hw = __bfloat162float(__float2bfloat16(v.w));
    uint2 wh = make_uint2(packbf(v.x, v.y), packbf(v.z, v.w));
    uint2 wl = make_uint2(packbf(v.x - hx, v.y - hy), packbf(v.z - hz, v.w - hw));
    *reinterpret_cast<uint2*>(dh + (size_t)off * 4) = wh;
    *reinterpret_cast<uint2*>(dl + (size_t)off * 4) = wl;
}

// =======================================================================
// K1: dual GEMM v2 (cp.async + ldmatrix, 3-stage), 3-term split-bf16.
// mode 0: g_Whb(bf16) = H@W, + fused e_src/e_dst scores.
// mode 1: g_R(fp32)   = H@res_W + res_b.
// Tile 128x128, BK=32, K=256 (8 iters), 256 thr.
// =======================================================================
#define PAS2 20
#define PBN2 68
#define AMAT (128 * PAS2)         // 2560 words per A matrix
#define ASTG (2 * AMAT)           // hi+lo
#define BMAT (32 * PBN2)          // 2176 words per B matrix
#define BSTG (2 * BMAT)
#define DG_SMEM (3 * (ASTG + BSTG) * 4)   // 113664 bytes

__global__ __launch_bounds__(256, 2) void dual_gemm(
    const float* __restrict__ res_b, const float* __restrict__ a_attn)
{
    extern __shared__ uint32_t smem_u[];
    const int mode = blockIdx.z;
    const int m0 = blockIdx.y * 128, n0 = blockIdx.x * 128;
    const int hn = blockIdx.x;
    const int tid = threadIdx.x;
    const int wid = tid >> 5, lane = tid & 31;
    const int wm = (wid & 3) * 32, wn = (wid >> 2) * 64;
    const int g = lane >> 2, tg = lane & 3;

    const __nv_bfloat16* __restrict__ Bh_g = mode ? g_B1h : g_B0h;
    const __nv_bfloat16* __restrict__ Bl_g = mode ? g_B1l : g_B0l;

    uint32_t sbase = (uint32_t)__cvta_generic_to_shared(smem_u);
    const uint32_t aB = sbase;
    const uint32_t bB = sbase + 3 * ASTG * 4;

    float4 acc[2][8];
#pragma unroll
    for (int mt = 0; mt < 2; mt++)
#pragma unroll
        for (int nt = 0; nt < 8; nt++) acc[mt][nt] = make_float4(0.f,0.f,0.f,0.f);

    auto issue = [&](int slot, int k0) {
#pragma unroll
        for (int i = 0; i < 2; i++) {
            int c = tid + i * 256;                  // 0..511
            int r = c >> 2, seg = c & 3;
            size_t si = (size_t)(m0 + r) * INF + k0 + seg * 8;
            uint32_t d = aB + (slot * ASTG + r * PAS2 + seg * 4) * 4;
            CP16(d, g_Hh + si);
            CP16(d + AMAT * 4, g_Hl + si);
        }
#pragma unroll
        for (int i = 0; i < 2; i++) {
            int c = tid + i * 256;
            int kr = c >> 4, sg = c & 15;
            size_t si = (size_t)(k0 + kr) * FEAT + n0 + sg * 8;
            uint32_t d = bB + (slot * BSTG + kr * PBN2 + sg * 4) * 4;
            CP16(d, Bh_g + si);
            CP16(d + BMAT * 4, Bl_g + si);
        }
        CP_COMMIT();
    };

    auto compute = [&](int slot) {
        const uint32_t aw = aB + slot * ASTG * 4;
        const uint32_t bw = bB + slot * BSTG * 4;
        const int mtx = lane >> 3, mr = lane & 7;
#pragma unroll
        for (int kk2 = 0; kk2 < 2; kk2++) {
            uint32_t ah[2][4], al[2][4];
#pragma unroll
            for (int mt = 0; mt < 2; mt++) {
                int row = wm + mt * 16 + (mtx & 1) * 8 + mr;
                int colw = kk2 * 8 + (mtx >> 1) * 4;
                LDSM_X4(ah[mt], aw + (row * PAS2 + colw) * 4);
                LDSM_X4(al[mt], aw + (AMAT + row * PAS2 + colw) * 4);
            }
#pragma unroll
            for (int p = 0; p < 4; p++) {
                uint32_t bh[4], bl[4];
                int kr = kk2 * 16 + (mtx & 1) * 8 + mr;
                int nb = wn + p * 16 + (mtx >> 1) * 8;
                LDSM_X4T(bh, bw + (kr * PBN2 + (nb >> 1)) * 4);
                LDSM_X4T(bl, bw + (BMAT + kr * PBN2 + (nb >> 1)) * 4);
#pragma unroll
                for (int mt = 0; mt < 2; mt++) {
                    mma_bf16(acc[mt][2*p],   ah[mt], bh[0], bh[1]);
                    mma_bf16(acc[mt][2*p],   ah[mt], bl[0], bl[1]);
                    mma_bf16(acc[mt][2*p],   al[mt], bh[0], bh[1]);
                    mma_bf16(acc[mt][2*p+1], ah[mt], bh[2], bh[3]);
                    mma_bf16(acc[mt][2*p+1], ah[mt], bl[2], bl[3]);
                    mma_bf16(acc[mt][2*p+1], al[mt], bh[2], bh[3]);
                }
            }
        }
    };

    const int NIT = INF / 32;                       // 8
    issue(0, 0);
    issue(1, 32);
    for (int it = 0; it < NIT; it++) {
        if (it + 2 < NIT) { CP_WAIT(1); } else { CP_WAIT(0); }
        __syncthreads();
        if (it + 2 < NIT) issue((it + 2) % 3, (it + 2) * 32);
        compute(it % 3);
    }

    // ---- epilogue ----
#pragma unroll
    for (int mt = 0; mt < 2; mt++) {
        int r0 = m0 + wm + mt * 16 + g;
#pragma unroll
        for (int nt = 0; nt < 8; nt++) {
            int cc = n0 + wn + nt * 8 + 2 * tg;
            float4 v = acc[mt][nt];
            if (mode) {
                float bv0 = res_b[cc], bv1 = res_b[cc + 1];
                float2 p0 = make_float2(v.x + bv0, v.y + bv1);
                float2 p1 = make_float2(v.z + bv0, v.w + bv1);
                *reinterpret_cast<float2*>(g_R + (size_t)r0 * FEAT + cc)       = p0;
                *reinterpret_cast<float2*>(g_R + (size_t)(r0 + 8) * FEAT + cc) = p1;
            } else {
                __nv_bfloat162 q0, q1;
                q0.x = __float2bfloat16(v.x); q0.y = __float2bfloat16(v.y);
                q1.x = __float2bfloat16(v.z); q1.y = __float2bfloat16(v.w);
                *reinterpret_cast<__nv_bfloat162*>(g_Whb + (size_t)r0 * FEAT + cc)       = q0;
                *reinterpret_cast<__nv_bfloat162*>(g_Whb + (size_t)(r0 + 8) * FEAT + cc) = q1;
            }
        }
    }

    if (mode == 0) {
        // reuse dynamic smem (mainloop done) for score reduction buffers
        float* fs  = reinterpret_cast<float*>(smem_u);
        float* sas = fs;            // [128]
        float* sad = fs + 128;      // [128]
        float* sE  = fs + 256;      // [2][128]
        float* sD  = fs + 512;      // [2][128]
        __syncthreads();
        if (tid < 128)      sas[tid]       = a_attn[hn * 256 + tid];
        else                sad[tid - 128] = a_attn[hn * 256 + 128 + (tid - 128)];
        __syncthreads();

        float ps[2][2] = {{0.f,0.f},{0.f,0.f}};
        float pd[2][2] = {{0.f,0.f},{0.f,0.f}};
#pragma unroll
        for (int mt = 0; mt < 2; mt++)
#pragma unroll
            for (int nt = 0; nt < 8; nt++) {
                int c = wn + nt * 8 + 2 * tg;
                float4 v = acc[mt][nt];
                float a0 = sas[c], a1 = sas[c + 1];
                float d0 = sad[c], d1 = sad[c + 1];
                ps[mt][0] += v.x * a0 + v.y * a1;
                ps[mt][1] += v.z * a0 + v.w * a1;
                pd[mt][0] += v.x * d0 + v.y * d1;
                pd[mt][1] += v.z * d0 + v.w * d1;
            }
#pragma unroll
        for (int mt = 0; mt < 2; mt++)
#pragma unroll
            for (int q = 0; q < 2; q++) {
                ps[mt][q] += __shfl_xor_sync(0xffffffffu, ps[mt][q], 1);
                ps[mt][q] += __shfl_xor_sync(0xffffffffu, ps[mt][q], 2);
                pd[mt][q] += __shfl_xor_sync(0xffffffffu, pd[mt][q], 1);
                pd[mt][q] += __shfl_xor_sync(0xffffffffu, pd[mt][q], 2);
            }
        const int wc = wid >> 2;
        if (tg == 0) {
#pragma unroll
            for (int mt = 0; mt < 2; mt++) {
                int r = wm + mt * 16 + g;
                sE[wc * 128 + r]     = ps[mt][0];
                sE[wc * 128 + r + 8] = ps[mt][1];
                sD[wc * 128 + r]     = pd[mt][0];
                sD[wc * 128 + r + 8] = pd[mt][1];
            }
        }
        __syncthreads();
        if (tid < 128) {
            g_es[(size_t)(m0 + tid) * NH + hn] = sE[tid] + sE[128 + tid];
            g_ed[(size_t)(m0 + tid) * NH + hn] = sD[tid] + sD[128 + tid];
        }
    }
}

// ------------------------------------- K3: softmax (no max pass, lean logit)
__global__ __launch_bounds__(256) void softmax_kernel(
    const float* __restrict__ Amat, float* __restrict__ alpha_out)
{
    __shared__ float s_es[8];
    __shared__ float s_stat[8];
    __shared__ float red[8][8];
    __shared__ float s_redsum[8];
    __shared__ float s_inv;

    const int bi = blockIdx.x;
    const int b = bi >> 10, i = bi & 1023;
    const int t = threadIdx.x, wid = t >> 5, lane = t & 31;

    const float* arow = Amat + (size_t)bi * Cc;
    float av[4], psum = 0.f;
#pragma unroll
    for (int jj = 0; jj < 4; jj++) {
        int j = t + jj * 256;
        av[jj] = arow[j];
        psum += av[jj];
    }
#pragma unroll
    for (int o = 16; o; o >>= 1) psum += __shfl_xor_sync(0xffffffffu, psum, o);
    if (!lane) s_redsum[wid] = psum;
    if (t < 8) s_es[t] = g_es[(size_t)bi * NH + t];
    __syncthreads();
    if (t == 0) {
        float s = 0.f;
#pragma unroll
        for (int w = 0; w < 8; w++) s += s_redsum[w];
        s_inv = 1.0f / (s + 1e-8f);
    }
    __syncthreads();

    const float inv = s_inv;
    float es[8];
#pragma unroll
    for (int h = 0; h < 8; h++) es[h] = s_es[h];

    // constants: fold (1/TEMP)*log2(e) into leaky coefficients and base
    const float CT  = 0.96179669f;      // (1/1.5)*log2(e)
    const float CT5 = 0.19235934f;      // 0.2 * CT
    float vv[4][8];
    float lsum[8];
#pragma unroll
    for (int h = 0; h < 8; h++) lsum[h] = 0.f;

#pragma unroll
    for (int jj = 0; jj < 4; jj++) {
        int j = t + jj * 256;
        const float4* edp = reinterpret_cast<const float4*>(g_ed + ((size_t)b * Cc + j) * NH);
        float4 e0 = edp[0], e1 = edp[1];
        float ed[8] = {e0.x,e0.y,e0.z,e0.w,e1.x,e1.y,e1.z,e1.w};
        float aval = av[jj];
        bool mk = (aval > 0.f) || (j == i);
        // base = (A_norm + (mk?0:-1e9)) * CT ; masked -> ex2 flushes to 0
        float base = fmaf(aval * inv, CT, mk ? 0.f : -9.6179667e8f);
#pragma unroll
        for (int h = 0; h < 8; h++) {
            float s = es[h] + ed[h];
            float c = s > 0.f ? CT : CT5;          // leaky slope folded
            float v = fmaf(s, c, base);
            float ev;
            asm("ex2.approx.f32 %0, %1;" : "=f"(ev) : "f"(v));
            vv[jj][h] = ev;
            lsum[h] += ev;
        }
    }
#pragma unroll
    for (int h = 0; h < 8; h++)
#pragma unroll
        for (int o = 16; o; o >>= 1)
            lsum[h] += __shfl_xor_sync(0xffffffffu, lsum[h], o);
    if (!lane) {
#pragma unroll
        for (int h = 0; h < 8; h++) red[wid][h] = lsum[h];
    }
    __syncthreads();
    if (t < 8) {
        float s = 0.f;
#pragma unroll
        for (int w = 0; w < 8; w++) s += red[w][t];
        s_stat[t] = 1.0f / s;
    }
    __syncthreads();
    float ish[8];
#pragma unroll
    for (int h = 0; h < 8; h++) ish[h] = s_stat[h];

    // alpha (b,i,j,h) fp32 output — coalesced 32B per thread
    float* oa = alpha_out + (size_t)bi * (Cc * NH);
#pragma unroll
    for (int jj = 0; jj < 4; jj++) {
        int j = t + jj * 256;
#pragma unroll
        for (int h = 0; h < 8; h++) vv[jj][h] *= ish[h];   // normalize once
        float4 o0 = make_float4(vv[jj][0], vv[jj][1], vv[jj][2], vv[jj][3]);
        float4 o1 = make_float4(vv[jj][4], vv[jj][5], vv[jj][6], vv[jj][7]);
        *reinterpret_cast<float4*>(oa + (size_t)j * NH)     = o0;
        *reinterpret_cast<float4*>(oa + (size_t)j * NH + 4) = o1;
    }
    // alphaT (b,h,i,j) bf16 scratch for aggr
#pragma unroll
    for (int h = 0; h < 8; h++) {
        __nv_bfloat16* ot = g_alphaTb + (((size_t)(b * NH + h)) * Cc + i) * Cc;
#pragma unroll
        for (int jj = 0; jj < 4; jj++) {
            int j = t + jj * 256;
            ot[j] = __float2bfloat16(vv[jj][h]);
        }
    }
}

// =======================================================================
// K4: aggr GEMM. per (b,h): Hout[1024,128] = alphaT@Whb + R.
// 128x128 tile, BK=32, 256 thr, 3-stage cp.async + ldmatrix.
// =======================================================================
#define PAS 20
#define PBS 68
#define A_STG (128 * PAS)
#define B_STG (32 * PBS)
#define AGGR_SMEM (3 * (A_STG + B_STG) * 4)   // 56832 bytes

__global__ __launch_bounds__(256, 2) void aggr_bf16()
{
    extern __shared__ uint32_t smem_u[];
    const int z = blockIdx.z;
    const int b = z >> 3, h = z & 7;
    const __nv_bfloat16* __restrict__ A  = g_alphaTb + (size_t)z * Cc * Cc;
    const __nv_bfloat16* __restrict__ Bp = g_Whb + (size_t)b * Cc * FEAT + h * OF;
    const float* __restrict__ R = g_R    + (size_t)b * Cc * FEAT + h * OF;
    float*       __restrict__ C = g_Hout + (size_t)b * Cc * FEAT + h * OF;

    const int m0 = blockIdx.y * 128;
    const int tid = threadIdx.x;
    const int wid = tid >> 5, lane = tid & 31;
    const int wm = (wid & 3) * 32, wn = (wid >> 2) * 64;
    const int g = lane >> 2, tg = lane & 3;

    uint32_t sbase = (uint32_t)__cvta_generic_to_shared(smem_u);
    const uint32_t aBase = sbase;
    const uint32_t bBase = sbase + 3 * A_STG * 4;

    float4 acc[2][8];
#pragma unroll
    for (int mt = 0; mt < 2; mt++)
#pragma unroll
        for (int nt = 0; nt < 8; nt++) acc[mt][nt] = make_float4(0.f,0.f,0.f,0.f);

    auto issue = [&](int slot, int k0) {
#pragma unroll
        for (int i = 0; i < 2; i++) {
            int c = tid + i * 256;
            int r = c >> 2, seg = c & 3;
            const __nv_bfloat16* src = A + (size_t)(m0 + r) * Cc + k0 + seg * 8;
            uint32_t dst = aBase + (slot * A_STG + r * PAS + seg * 4) * 4;
            CP16(dst, src);
        }
#pragma unroll
        for (int i = 0; i < 2; i++) {
            int c = tid + i * 256;
            int kr = c >> 4, seg = c & 15;
            const __nv_bfloat16* src = Bp + (size_t)(k0 + kr) * FEAT + seg * 8;
            uint32_t dst = bBase + (slot * B_STG + kr * PBS + seg * 4) * 4;
            CP16(dst, src);
        }
        CP_COMMIT();
    };

    auto compute = [&](int slot) {
        const uint32_t aw = aBase + slot * A_STG * 4;
        const uint32_t bw = bBase + slot * B_STG * 4;
        const int mtx = lane >> 3;
        const int mr  = lane & 7;
#pragma unroll
        for (int kk2 = 0; kk2 < 2; kk2++) {
            uint32_t af[2][4];
#pragma unroll
            for (int mt = 0; mt < 2; mt++) {
                int row = wm + mt * 16 + (mtx & 1) * 8 + mr;
                int col = kk2 * 8 + (mtx >> 1) * 4;
                LDSM_X4(af[mt], aw + (row * PAS + col) * 4);
            }
#pragma unroll
            for (int p = 0; p < 4; p++) {
                uint32_t bf[4];
                int kr = kk2 * 16 + (mtx & 1) * 8 + mr;
                int nb = wn + p * 16 + (mtx >> 1) * 8;
                LDSM_X4T(bf, bw + (kr * PBS + (nb >> 1)) * 4);
#pragma unroll
                for (int mt = 0; mt < 2; mt++) {
                    mma_bf16(acc[mt][2 * p],     af[mt], bf[0], bf[1]);
                    mma_bf16(acc[mt][2 * p + 1], af[mt], bf[2], bf[3]);
                }
            }
        }
    };

    const int NIT = Cc / 32;
    issue(0, 0);
    issue(1, 32);
    for (int it = 0; it < NIT; it++) {
        if (it + 2 < NIT) { CP_WAIT(1); } else { CP_WAIT(0); }
        __syncthreads();
        if (it + 2 < NIT) issue((it + 2) % 3, (it + 2) * 32);
        compute(it % 3);
    }

#pragma unroll
    for (int mt = 0; mt < 2; mt++) {
        int r0 = m0 + wm + mt * 16 + g;
#pragma unroll
        for (int nt = 0; nt < 8; nt++) {
            int cc = wn + nt * 8 + 2 * tg;
            float4 v = acc[mt][nt];
            float2 ra  = *reinterpret_cast<const float2*>(R + (size_t)r0 * FEAT + cc);
            float2 rbv = *reinterpret_cast<const float2*>(R + (size_t)(r0 + 8) * FEAT + cc);
            float2 p0 = make_float2(v.x + ra.x,  v.y + ra.y);
            float2 p1 = make_float2(v.z + rbv.x, v.w + rbv.y);
            *reinterpret_cast<float2*>(C + (size_t)r0 * FEAT + cc)       = p0;
            *reinterpret_cast<float2*>(C + (size_t)(r0 + 8) * FEAT + cc) = p1;
        }
    }
}

// ------------------------------------------------- K5: LayerNorm + ReLU ----
__global__ __launch_bounds__(256) void ln_kernel(
    const float* __restrict__ gamma, const float* __restrict__ beta,
    float* __restrict__ out)
{
    __shared__ float rs[8], rs2[8];
    __shared__ float s_mu, s_rstd;
    const int bi = blockIdx.x;
    const int t = threadIdx.x, wid = t >> 5, lane = t & 31;
    const float* x = g_Hout + (size_t)bi * FEAT;
    float xs[4], s = 0.f, s2 = 0.f;
#pragma unroll
    for (int jj = 0; jj < 4; jj++) {
        float v = x[t + jj * 256];
        xs[jj] = v; s += v; s2 += v * v;
    }
#pragma unroll
    for (int o = 16; o; o >>= 1) {
        s  += __shfl_xor_sync(0xffffffffu, s, o);
        s2 += __shfl_xor_sync(0xffffffffu, s2, o);
    }
    if (!lane) { rs[wid] = s; rs2[wid] = s2; }
    __syncthreads();
    if (t == 0) {
        float ts = 0.f, ts2 = 0.f;
#pragma unroll
        for (int w = 0; w < 8; w++) { ts += rs[w]; ts2 += rs2[w]; }
        float mu = ts * (1.0f / FEAT);
        float var = ts2 * (1.0f / FEAT) - mu * mu;
        s_mu = mu;
        s_rstd = rsqrtf(var + 1e-5f);
    }
    __syncthreads();
    const float mu = s_mu, rstd = s_rstd;
#pragma unroll
    for (int jj = 0; jj < 4; jj++) {
        int f = t + jj * 256;
        float y = (xs[jj] - mu) * rstd * gamma[f] + beta[f];
        out[(size_t)bi * FEAT + f] = fmaxf(y, 0.f);
    }
}

// --------------------------------------------------------------------------
extern "C" void kernel_launch(void* const* d_in, const int* in_sizes, int n_in,
                              void* d_out, int out_size)
{
    const float* H      = (const float*)d_in[0];
    const float* Amat   = (const float*)d_in[1];
    const float* W      = (const float*)d_in[2];
    const float* a_attn = (const float*)d_in[3];
    const float* res_W  = (const float*)d_in[4];
    const float* res_b  = (const float*)d_in[5];
    const float* gamma  = (const float*)d_in[6];
    const float* beta   = (const float*)d_in[7];
    float* out = (float*)d_out;

    static bool smem_set = false;
    if (!smem_set) {
        cudaFuncSetAttribute(dual_gemm,
            cudaFuncAttributeMaxDynamicSharedMemorySize, DG_SMEM);
        cudaFuncSetAttribute(aggr_bf16,
            cudaFuncAttributeMaxDynamicSharedMemorySize, AGGR_SMEM);
        smem_set = true;
    }

    // K0: split operands into bf16 hi/lo
    const int prep_tot = (H_ELE + 2 * W_ELE) / 4;
    prep_kernel<<<(prep_tot + 255) / 256, 256>>>(H, W, res_W);

    // K1: merged Wh(+scores) and R GEMMs, pipelined
    dim3 g1(FEAT / 128, ROWS / 128, 2);
    dual_gemm<<<g1, 256, DG_SMEM>>>(res_b, a_attn);

    softmax_kernel<<<ROWS, 256>>>(Amat, out + X_ELEMS);

    dim3 g4(1, Cc / 128, Bb * NH);
    aggr_bf16<<<g4, 256, AGGR_SMEM>>>();

    ln_kernel<<<ROWS, 256>>>(gamma, beta, out);
}